// round 2
// baseline (speedup 1.0000x reference)
#include <cuda_runtime.h>
#include <math_constants.h>

// Problem constants
#define BATCH   2
#define SEQ     2048
#define T_TOK   4096          // BATCH*SEQ
#define DMODEL  1024
#define PROJ    256
#define HEADS   16
#define DH      64

// Scratch (device globals: no allocations allowed)
__device__ float g_cq [T_TOK * PROJ];
__device__ float g_ckv[T_TOK * PROJ];
__device__ float g_Q  [T_TOK * DMODEL];
__device__ float g_KV [T_TOK * 2 * DMODEL];
__device__ float g_AO [T_TOK * DMODEL];

// ---------------------------------------------------------------------------
// Tiled SGEMM: C[M,N] = A[M,K] @ B  (B is [K,N] if !TRANSB, [N,K] if TRANSB)
// 64x64 tile, BK=16, 256 threads, 4x4 per-thread micro-tile.
// ---------------------------------------------------------------------------
template <bool TRANSB>
__global__ __launch_bounds__(256) void sgemm64(
    const float* __restrict__ A, const float* __restrict__ B,
    float* __restrict__ C, int M, int N, int K)
{
    __shared__ float As[16][68];   // As[k][m]
    __shared__ float Bs[16][68];   // Bs[k][n]
    const int tid = threadIdx.x;
    const int tx = tid & 15, ty = tid >> 4;
    const int bm = blockIdx.y * 64, bn = blockIdx.x * 64;

    float acc[4][4] = {};

    for (int k0 = 0; k0 < K; k0 += 16) {
        // Load A tile (64 x 16) transposed into As[k][m]
        {
            const int m  = tid >> 2;
            const int kc = (tid & 3) << 2;
            float4 a = *(const float4*)&A[(size_t)(bm + m) * K + k0 + kc];
            As[kc + 0][m] = a.x; As[kc + 1][m] = a.y;
            As[kc + 2][m] = a.z; As[kc + 3][m] = a.w;
        }
        if (!TRANSB) {
            const int kr = tid >> 4;
            const int nc = (tid & 15) << 2;
            *(float4*)&Bs[kr][nc] =
                *(const float4*)&B[(size_t)(k0 + kr) * N + bn + nc];
        } else {
            const int n  = tid >> 2;
            const int kc = (tid & 3) << 2;
            float4 b = *(const float4*)&B[(size_t)(bn + n) * K + k0 + kc];
            Bs[kc + 0][n] = b.x; Bs[kc + 1][n] = b.y;
            Bs[kc + 2][n] = b.z; Bs[kc + 3][n] = b.w;
        }
        __syncthreads();

#pragma unroll
        for (int k = 0; k < 16; k++) {
            float4 a = *(const float4*)&As[k][ty << 2];
            float4 b = *(const float4*)&Bs[k][tx << 2];
            float av[4] = {a.x, a.y, a.z, a.w};
            float bv[4] = {b.x, b.y, b.z, b.w};
#pragma unroll
            for (int i = 0; i < 4; i++)
#pragma unroll
                for (int j = 0; j < 4; j++)
                    acc[i][j] += av[i] * bv[j];
        }
        __syncthreads();
    }

#pragma unroll
    for (int i = 0; i < 4; i++) {
        float4 c = make_float4(acc[i][0], acc[i][1], acc[i][2], acc[i][3]);
        *(float4*)&C[(size_t)(bm + (ty << 2) + i) * N + bn + (tx << 2)] = c;
    }
}

// ---------------------------------------------------------------------------
// LayerNorm over width=256, one block per row, in-place.
// ---------------------------------------------------------------------------
__global__ __launch_bounds__(256) void ln256(
    float* __restrict__ X, const float* __restrict__ g,
    const float* __restrict__ b)
{
    const int row = blockIdx.x, tid = threadIdx.x;
    float v = X[(size_t)row * 256 + tid];

    __shared__ float red[8];
    float s = v;
#pragma unroll
    for (int m = 16; m > 0; m >>= 1) s += __shfl_xor_sync(0xffffffffu, s, m);
    if ((tid & 31) == 0) red[tid >> 5] = s;
    __syncthreads();
    float tot = 0.f;
#pragma unroll
    for (int i = 0; i < 8; i++) tot += red[i];
    const float mu = tot * (1.0f / 256.0f);
    const float d = v - mu;

    s = d * d;
    __syncthreads();
#pragma unroll
    for (int m = 16; m > 0; m >>= 1) s += __shfl_xor_sync(0xffffffffu, s, m);
    if ((tid & 31) == 0) red[tid >> 5] = s;
    __syncthreads();
    tot = 0.f;
#pragma unroll
    for (int i = 0; i < 8; i++) tot += red[i];
    const float var = tot * (1.0f / 256.0f);

    X[(size_t)row * 256 + tid] = d * rsqrtf(var + 1e-5f) * g[tid] + b[tid];
}

// ---------------------------------------------------------------------------
// Causal flash attention, fp32. One block per (qtile=64, head, batch).
// 256 threads, 16x16 layout; each thread owns a 4(q) x 4(k or d) fragment.
// FULL 64x64 tiles staged: each thread loads 4 float4s per tile (d = 0..63).
// KV layout: KV[token][0:1024]=K (h*64+d), KV[token][1024:2048]=V.
// ---------------------------------------------------------------------------
__global__ __launch_bounds__(256) void attn_kernel(
    const float* __restrict__ Q, const float* __restrict__ KV,
    float* __restrict__ O)
{
    extern __shared__ float sm[];
    float* QT = sm;                 // [64][68]  QT[d][q]
    float* KT = sm + 64 * 68;       // [64][68]  KT[d][k]
    float* Vs = sm + 2 * 64 * 68;   // [64][68]  Vs[k][d]
    float* PT = sm + 3 * 64 * 68;   // [64][68]  PT[k][q]

    const int tid = threadIdx.x;
    const int tx = tid & 15, ty = tid >> 4;
    const int qt = blockIdx.x, h = blockIdx.y, b = blockIdx.z;
    const size_t tok0 = (size_t)b * SEQ + (size_t)qt * 64;

    // Stage Q tile transposed: QT[d][q]  (full 64 d per row: 4 float4/thread)
    {
        const int q = tid >> 2;
        const int dlo = (tid & 3) << 2;
#pragma unroll
        for (int db = 0; db < 64; db += 16) {
            const int dc = db + dlo;
            float4 qv = *(const float4*)&Q[(tok0 + q) * DMODEL + h * DH + dc];
            QT[(dc + 0) * 68 + q] = qv.x; QT[(dc + 1) * 68 + q] = qv.y;
            QT[(dc + 2) * 68 + q] = qv.z; QT[(dc + 3) * 68 + q] = qv.w;
        }
    }

    float o[4][4] = {};
    float mrow[4] = {-CUDART_INF_F, -CUDART_INF_F, -CUDART_INF_F, -CUDART_INF_F};
    float lrow[4] = {};

    for (int kt = 0; kt <= qt; kt++) {
        const size_t ktok0 = (size_t)b * SEQ + (size_t)kt * 64;
        __syncthreads();   // prev PV reads / Q staging complete before overwrite
        {
            const int k = tid >> 2;
            const int dlo = (tid & 3) << 2;
            const float* kvrow = &KV[(ktok0 + k) * (2 * DMODEL) + h * DH];
#pragma unroll
            for (int db = 0; db < 64; db += 16) {
                const int dc = db + dlo;
                float4 kv = *(const float4*)(kvrow + dc);
                KT[(dc + 0) * 68 + k] = kv.x; KT[(dc + 1) * 68 + k] = kv.y;
                KT[(dc + 2) * 68 + k] = kv.z; KT[(dc + 3) * 68 + k] = kv.w;
                *(float4*)&Vs[k * 68 + dc] = *(const float4*)(kvrow + DMODEL + dc);
            }
        }
        __syncthreads();

        // S = Q K^T (this tile)
        float s[4][4] = {};
#pragma unroll
        for (int d = 0; d < 64; d++) {
            float4 qv = *(const float4*)&QT[d * 68 + (ty << 2)];
            float4 kv = *(const float4*)&KT[d * 68 + (tx << 2)];
            float qa[4] = {qv.x, qv.y, qv.z, qv.w};
            float ka[4] = {kv.x, kv.y, kv.z, kv.w};
#pragma unroll
            for (int i = 0; i < 4; i++)
#pragma unroll
                for (int j = 0; j < 4; j++)
                    s[i][j] += qa[i] * ka[j];
        }

        const float scale = 0.125f;   // 1/sqrt(64)
        if (kt == qt) {
#pragma unroll
            for (int i = 0; i < 4; i++)
#pragma unroll
                for (int j = 0; j < 4; j++) {
                    const int qg = (ty << 2) + i, kg = (tx << 2) + j;
                    s[i][j] = (kg > qg) ? -CUDART_INF_F : s[i][j] * scale;
                }
        } else {
#pragma unroll
            for (int i = 0; i < 4; i++)
#pragma unroll
                for (int j = 0; j < 4; j++) s[i][j] *= scale;
        }

        // Online softmax (row reductions over the 16 tx lanes)
#pragma unroll
        for (int i = 0; i < 4; i++) {
            float mt = fmaxf(fmaxf(s[i][0], s[i][1]), fmaxf(s[i][2], s[i][3]));
#pragma unroll
            for (int msk = 1; msk < 16; msk <<= 1)
                mt = fmaxf(mt, __shfl_xor_sync(0xffffffffu, mt, msk));
            const float mnew = fmaxf(mrow[i], mt);
            const float corr = __expf(mrow[i] - mnew);
            mrow[i] = mnew;
            float psum = 0.f;
#pragma unroll
            for (int j = 0; j < 4; j++) {
                const float p = __expf(s[i][j] - mnew);
                s[i][j] = p;
                psum += p;
            }
#pragma unroll
            for (int msk = 1; msk < 16; msk <<= 1)
                psum += __shfl_xor_sync(0xffffffffu, psum, msk);
            lrow[i] = lrow[i] * corr + psum;
#pragma unroll
            for (int j = 0; j < 4; j++) o[i][j] *= corr;
        }

        // Stage P transposed: PT[k][q]
#pragma unroll
        for (int i = 0; i < 4; i++)
#pragma unroll
            for (int j = 0; j < 4; j++)
                PT[((tx << 2) + j) * 68 + (ty << 2) + i] = s[i][j];
        __syncthreads();

        // O += P V
#pragma unroll
        for (int k = 0; k < 64; k++) {
            float4 pv = *(const float4*)&PT[k * 68 + (ty << 2)];
            float4 vv = *(const float4*)&Vs[k * 68 + (tx << 2)];
            float pa[4] = {pv.x, pv.y, pv.z, pv.w};
            float va[4] = {vv.x, vv.y, vv.z, vv.w};
#pragma unroll
            for (int i = 0; i < 4; i++)
#pragma unroll
                for (int j = 0; j < 4; j++)
                    o[i][j] += pa[i] * va[j];
        }
    }

    // Normalize and write out: O[token][h*64 + d]
#pragma unroll
    for (int i = 0; i < 4; i++) {
        const float inv = 1.0f / lrow[i];
        float4 c = make_float4(o[i][0] * inv, o[i][1] * inv,
                               o[i][2] * inv, o[i][3] * inv);
        *(float4*)&O[(tok0 + (ty << 2) + i) * DMODEL + h * DH + (tx << 2)] = c;
    }
}

// ---------------------------------------------------------------------------
// Launch
// ---------------------------------------------------------------------------
extern "C" void kernel_launch(void* const* d_in, const int* in_sizes, int n_in,
                              void* d_out, int out_size)
{
    const float* x     = (const float*)d_in[0];
    const float* W_dq  = (const float*)d_in[1];
    const float* W_uq  = (const float*)d_in[2];
    const float* q_g   = (const float*)d_in[3];
    const float* q_b   = (const float*)d_in[4];
    const float* W_dkv = (const float*)d_in[5];
    const float* W_ukv = (const float*)d_in[6];
    const float* kv_g  = (const float*)d_in[7];
    const float* kv_b  = (const float*)d_in[8];
    const float* W_o   = (const float*)d_in[9];
    float* out = (float*)d_out;

    float *cq, *ckv, *Qb, *KVb, *AO;
    cudaGetSymbolAddress((void**)&cq,  g_cq);
    cudaGetSymbolAddress((void**)&ckv, g_ckv);
    cudaGetSymbolAddress((void**)&Qb,  g_Q);
    cudaGetSymbolAddress((void**)&KVb, g_KV);
    cudaGetSymbolAddress((void**)&AO,  g_AO);

    const dim3 blk(256);

    // Down-projections: [4096,1024] @ [1024,256]
    sgemm64<false><<<dim3(PROJ / 64, T_TOK / 64), blk>>>(x, W_dq,  cq,  T_TOK, PROJ, DMODEL);
    sgemm64<false><<<dim3(PROJ / 64, T_TOK / 64), blk>>>(x, W_dkv, ckv, T_TOK, PROJ, DMODEL);

    // LayerNorms (in-place)
    ln256<<<T_TOK, 256>>>(cq,  q_g,  q_b);
    ln256<<<T_TOK, 256>>>(ckv, kv_g, kv_b);

    // Up-projections
    sgemm64<false><<<dim3(DMODEL / 64, T_TOK / 64), blk>>>(cq,  W_uq,  Qb,  T_TOK, DMODEL, PROJ);
    sgemm64<false><<<dim3(2 * DMODEL / 64, T_TOK / 64), blk>>>(ckv, W_ukv, KVb, T_TOK, 2 * DMODEL, PROJ);

    // Attention
    const size_t smem = 4 * 64 * 68 * sizeof(float);   // 69632 B
    cudaFuncSetAttribute(attn_kernel, cudaFuncAttributeMaxDynamicSharedMemorySize, (int)smem);
    attn_kernel<<<dim3(SEQ / 64, HEADS, BATCH), blk, smem>>>(Qb, KVb, AO);

    // Output projection: out = AO @ W_o^T
    sgemm64<true><<<dim3(DMODEL / 64, T_TOK / 64), blk>>>(AO, W_o, out, T_TOK, DMODEL, DMODEL);
}

// round 5
// speedup vs baseline: 1.1510x; 1.1510x over previous
#include <cuda_runtime.h>
#include <cuda_bf16.h>
#include <math_constants.h>
#include <cstdint>

// Problem constants
#define BATCH   2
#define SEQ     2048
#define T_TOK   4096
#define DMODEL  1024
#define PROJ    256
#define HEADS   16
#define DH      64

// Scratch (device globals: no allocations allowed)
__device__ float g_cq [T_TOK * PROJ];
__device__ float g_ckv[T_TOK * PROJ];
__device__ float g_Q  [T_TOK * DMODEL];
__device__ float g_KV [T_TOK * 2 * DMODEL];
__device__ float g_AO [T_TOK * DMODEL];

// ============================================================================
// Helpers
// ============================================================================
__device__ __forceinline__ void cvt_hilo2(float x, float y, uint32_t& h, uint32_t& l)
{
    __nv_bfloat162 hv = __floats2bfloat162_rn(x, y);          // x->lo half, y->hi half
    float rx = x - __bfloat162float(hv.x);
    float ry = y - __bfloat162float(hv.y);
    __nv_bfloat162 lv = __floats2bfloat162_rn(rx, ry);
    h = *(uint32_t*)&hv;
    l = *(uint32_t*)&lv;
}

__device__ __forceinline__ void mma16816(float* c, uint32_t a0, uint32_t a1,
                                         uint32_t a2, uint32_t a3,
                                         uint32_t b0, uint32_t b1)
{
    asm volatile(
        "mma.sync.aligned.m16n8k16.row.col.f32.bf16.bf16.f32 "
        "{%0,%1,%2,%3}, {%4,%5,%6,%7}, {%8,%9}, {%0,%1,%2,%3};\n"
        : "+f"(c[0]), "+f"(c[1]), "+f"(c[2]), "+f"(c[3])
        : "r"(a0), "r"(a1), "r"(a2), "r"(a3), "r"(b0), "r"(b1));
}

// ============================================================================
// mma_gemm: C[M,N](fp32) = A[M,K] @ B  via bf16 hi/lo split (3 MMA passes).
// B is [K,N] if !TRANSB (transposed during staging), [N,K] if TRANSB.
// CTA: 256 threads (8 warps), tile 128(M) x 128(N), K chunked by 32.
// Warp w computes the 64x32 sub-tile at (m = (w&1)*64, n = (w>>1)*32).
// SMEM tiles stored as packed u32 (2 bf16 along k), row stride PADW words.
// ============================================================================
#define PADW 21   // 16 data words (32 bf16) + 5 pad

__device__ __forceinline__ void stage_rowmajor_mma(
    const float* __restrict__ G, int ldg,
    uint32_t* __restrict__ sh, uint32_t* __restrict__ sl, int tid)
{
    // 128 rows x 32 floats = 1024 float4; 4 per thread.
#pragma unroll
    for (int i = 0; i < 4; i++) {
        const int f4id = i * 256 + tid;
        const int row = f4id >> 3;
        const int c4  = f4id & 7;
        float4 v = *(const float4*)&G[(size_t)row * ldg + c4 * 4];
        uint32_t h0, l0, h1, l1;
        cvt_hilo2(v.x, v.y, h0, l0);
        cvt_hilo2(v.z, v.w, h1, l1);
        const int w = row * PADW + c4 * 2;
        sh[w] = h0; sh[w + 1] = h1;
        sl[w] = l0; sl[w + 1] = l1;
    }
}

__device__ __forceinline__ void stage_transpose_mma(
    const float* __restrict__ G, int ldg,
    uint32_t* __restrict__ sh, uint32_t* __restrict__ sl, int tid)
{
    // B[K,N] slice: 32 k-rows x 128 n-cols -> sB[n][k]
    __nv_bfloat16* bh = (__nv_bfloat16*)sh;
    __nv_bfloat16* bl = (__nv_bfloat16*)sl;
#pragma unroll
    for (int i = 0; i < 4; i++) {
        const int f4id = i * 256 + tid;
        const int kr = f4id >> 5;
        const int n4 = f4id & 31;
        float4 v = *(const float4*)&G[(size_t)kr * ldg + n4 * 4];
        float vv[4] = {v.x, v.y, v.z, v.w};
#pragma unroll
        for (int j = 0; j < 4; j++) {
            const int n = n4 * 4 + j;
            __nv_bfloat16 h = __float2bfloat16(vv[j]);
            __nv_bfloat16 l = __float2bfloat16(vv[j] - __bfloat162float(h));
            bh[n * (2 * PADW) + kr] = h;
            bl[n * (2 * PADW) + kr] = l;
        }
    }
}

template <bool TRANSB>
__global__ __launch_bounds__(256) void mma_gemm(
    const float* __restrict__ A, const float* __restrict__ B,
    float* __restrict__ C, int N, int K)
{
    __shared__ uint32_t sA[2][128 * PADW];
    __shared__ uint32_t sB[2][128 * PADW];

    const int tid  = threadIdx.x;
    const int warp = tid >> 5, lane = tid & 31;
    const int g = lane >> 2, t = lane & 3;
    const int mi = (warp & 1) * 64;
    const int ni = (warp >> 1) * 32;
    const int bm = blockIdx.y * 128, bn = blockIdx.x * 128;

    float acc[4][4][4] = {};   // [mfrag][nfrag][reg]

    const int nchunks = K / 32;
    for (int c = 0; c < nchunks; c++) {
        const int k0 = c * 32;
        __syncthreads();   // previous chunk's fragment reads done
        stage_rowmajor_mma(A + (size_t)bm * K + k0, K, sA[0], sA[1], tid);
        if (TRANSB)
            stage_rowmajor_mma(B + (size_t)bn * K + k0, K, sB[0], sB[1], tid);
        else
            stage_transpose_mma(B + (size_t)k0 * N + bn, N, sB[0], sB[1], tid);
        __syncthreads();

        // 3 passes: (Ah,Bh), (Ah,Bl), (Al,Bh)
#pragma unroll
        for (int p = 0; p < 3; p++) {
            const uint32_t* pa = sA[(p == 2) ? 1 : 0];
            const uint32_t* pb = sB[(p == 1) ? 1 : 0];
#pragma unroll
            for (int k2 = 0; k2 < 2; k2++) {
                const int w0 = k2 * 8 + t;
                uint32_t af[4][4];
#pragma unroll
                for (int fm = 0; fm < 4; fm++) {
                    const int r0 = mi + fm * 16 + g;
                    af[fm][0] = pa[r0 * PADW + w0];
                    af[fm][1] = pa[(r0 + 8) * PADW + w0];
                    af[fm][2] = pa[r0 * PADW + w0 + 4];
                    af[fm][3] = pa[(r0 + 8) * PADW + w0 + 4];
                }
                uint32_t bf[4][2];
#pragma unroll
                for (int fn = 0; fn < 4; fn++) {
                    const int n0 = ni + fn * 8 + g;
                    bf[fn][0] = pb[n0 * PADW + w0];
                    bf[fn][1] = pb[n0 * PADW + w0 + 4];
                }
#pragma unroll
                for (int fm = 0; fm < 4; fm++)
#pragma unroll
                    for (int fn = 0; fn < 4; fn++)
                        mma16816(acc[fm][fn], af[fm][0], af[fm][1],
                                 af[fm][2], af[fm][3], bf[fn][0], bf[fn][1]);
            }
        }
    }

    // Epilogue: fragment layout c0,c1 -> (row g, col t*2), c2,c3 -> (row g+8)
#pragma unroll
    for (int fm = 0; fm < 4; fm++) {
        const int row = bm + mi + fm * 16 + g;
#pragma unroll
        for (int fn = 0; fn < 4; fn++) {
            const int col = bn + ni + fn * 8 + t * 2;
            *(float2*)&C[(size_t)row * N + col] =
                make_float2(acc[fm][fn][0], acc[fm][fn][1]);
            *(float2*)&C[(size_t)(row + 8) * N + col] =
                make_float2(acc[fm][fn][2], acc[fm][fn][3]);
        }
    }
}

// ---------------------------------------------------------------------------
// LayerNorm over width=256, one block per row, in-place.
// ---------------------------------------------------------------------------
__global__ __launch_bounds__(256) void ln256(
    float* __restrict__ X, const float* __restrict__ g,
    const float* __restrict__ b)
{
    const int row = blockIdx.x, tid = threadIdx.x;
    float v = X[(size_t)row * 256 + tid];

    __shared__ float red[8];
    float s = v;
#pragma unroll
    for (int m = 16; m > 0; m >>= 1) s += __shfl_xor_sync(0xffffffffu, s, m);
    if ((tid & 31) == 0) red[tid >> 5] = s;
    __syncthreads();
    float tot = 0.f;
#pragma unroll
    for (int i = 0; i < 8; i++) tot += red[i];
    const float mu = tot * (1.0f / 256.0f);
    const float d = v - mu;

    s = d * d;
    __syncthreads();
#pragma unroll
    for (int m = 16; m > 0; m >>= 1) s += __shfl_xor_sync(0xffffffffu, s, m);
    if ((tid & 31) == 0) red[tid >> 5] = s;
    __syncthreads();
    tot = 0.f;
#pragma unroll
    for (int i = 0; i < 8; i++) tot += red[i];
    const float var = tot * (1.0f / 256.0f);

    X[(size_t)row * 256 + tid] = d * rsqrtf(var + 1e-5f) * g[tid] + b[tid];
}

// ---------------------------------------------------------------------------
// Causal flash attention, fp32 (unchanged from R2 — correct).
// ---------------------------------------------------------------------------
__global__ __launch_bounds__(256) void attn_kernel(
    const float* __restrict__ Q, const float* __restrict__ KV,
    float* __restrict__ O)
{
    extern __shared__ float smf[];
    float* QT = smf;
    float* KT = smf + 64 * 68;
    float* Vs = smf + 2 * 64 * 68;
    float* PT = smf + 3 * 64 * 68;

    const int tid = threadIdx.x;
    const int tx = tid & 15, ty = tid >> 4;
    const int qt = blockIdx.x, h = blockIdx.y, b = blockIdx.z;
    const size_t tok0 = (size_t)b * SEQ + (size_t)qt * 64;

    {
        const int q = tid >> 2;
        const int dlo = (tid & 3) << 2;
#pragma unroll
        for (int db = 0; db < 64; db += 16) {
            const int dc = db + dlo;
            float4 qv = *(const float4*)&Q[(tok0 + q) * DMODEL + h * DH + dc];
            QT[(dc + 0) * 68 + q] = qv.x; QT[(dc + 1) * 68 + q] = qv.y;
            QT[(dc + 2) * 68 + q] = qv.z; QT[(dc + 3) * 68 + q] = qv.w;
        }
    }

    float o[4][4] = {};
    float mrow[4] = {-CUDART_INF_F, -CUDART_INF_F, -CUDART_INF_F, -CUDART_INF_F};
    float lrow[4] = {};

    for (int kt = 0; kt <= qt; kt++) {
        const size_t ktok0 = (size_t)b * SEQ + (size_t)kt * 64;
        __syncthreads();
        {
            const int k = tid >> 2;
            const int dlo = (tid & 3) << 2;
            const float* kvrow = &KV[(ktok0 + k) * (2 * DMODEL) + h * DH];
#pragma unroll
            for (int db = 0; db < 64; db += 16) {
                const int dc = db + dlo;
                float4 kv = *(const float4*)(kvrow + dc);
                KT[(dc + 0) * 68 + k] = kv.x; KT[(dc + 1) * 68 + k] = kv.y;
                KT[(dc + 2) * 68 + k] = kv.z; KT[(dc + 3) * 68 + k] = kv.w;
                *(float4*)&Vs[k * 68 + dc] = *(const float4*)(kvrow + DMODEL + dc);
            }
        }
        __syncthreads();

        float s[4][4] = {};
#pragma unroll
        for (int d = 0; d < 64; d++) {
            float4 qv = *(const float4*)&QT[d * 68 + (ty << 2)];
            float4 kv = *(const float4*)&KT[d * 68 + (tx << 2)];
            float qa[4] = {qv.x, qv.y, qv.z, qv.w};
            float ka[4] = {kv.x, kv.y, kv.z, kv.w};
#pragma unroll
            for (int i = 0; i < 4; i++)
#pragma unroll
                for (int j = 0; j < 4; j++)
                    s[i][j] += qa[i] * ka[j];
        }

        const float scale = 0.125f;
        if (kt == qt) {
#pragma unroll
            for (int i = 0; i < 4; i++)
#pragma unroll
                for (int j = 0; j < 4; j++) {
                    const int qg = (ty << 2) + i, kg = (tx << 2) + j;
                    s[i][j] = (kg > qg) ? -CUDART_INF_F : s[i][j] * scale;
                }
        } else {
#pragma unroll
            for (int i = 0; i < 4; i++)
#pragma unroll
                for (int j = 0; j < 4; j++) s[i][j] *= scale;
        }

#pragma unroll
        for (int i = 0; i < 4; i++) {
            float mt = fmaxf(fmaxf(s[i][0], s[i][1]), fmaxf(s[i][2], s[i][3]));
#pragma unroll
            for (int msk = 1; msk < 16; msk <<= 1)
                mt = fmaxf(mt, __shfl_xor_sync(0xffffffffu, mt, msk));
            const float mnew = fmaxf(mrow[i], mt);
            const float corr = __expf(mrow[i] - mnew);
            mrow[i] = mnew;
            float psum = 0.f;
#pragma unroll
            for (int j = 0; j < 4; j++) {
                const float p = __expf(s[i][j] - mnew);
                s[i][j] = p;
                psum += p;
            }
#pragma unroll
            for (int msk = 1; msk < 16; msk <<= 1)
                psum += __shfl_xor_sync(0xffffffffu, psum, msk);
            lrow[i] = lrow[i] * corr + psum;
#pragma unroll
            for (int j = 0; j < 4; j++) o[i][j] *= corr;
        }

#pragma unroll
        for (int i = 0; i < 4; i++)
#pragma unroll
            for (int j = 0; j < 4; j++)
                PT[((tx << 2) + j) * 68 + (ty << 2) + i] = s[i][j];
        __syncthreads();

#pragma unroll
        for (int k = 0; k < 64; k++) {
            float4 pv = *(const float4*)&PT[k * 68 + (ty << 2)];
            float4 vv = *(const float4*)&Vs[k * 68 + (tx << 2)];
            float pa[4] = {pv.x, pv.y, pv.z, pv.w};
            float va[4] = {vv.x, vv.y, vv.z, vv.w};
#pragma unroll
            for (int i = 0; i < 4; i++)
#pragma unroll
                for (int j = 0; j < 4; j++)
                    o[i][j] += pa[i] * va[j];
        }
    }

#pragma unroll
    for (int i = 0; i < 4; i++) {
        const float inv = 1.0f / lrow[i];
        float4 c = make_float4(o[i][0] * inv, o[i][1] * inv,
                               o[i][2] * inv, o[i][3] * inv);
        *(float4*)&O[(tok0 + (ty << 2) + i) * DMODEL + h * DH + (tx << 2)] = c;
    }
}

// ---------------------------------------------------------------------------
// Launch
// ---------------------------------------------------------------------------
extern "C" void kernel_launch(void* const* d_in, const int* in_sizes, int n_in,
                              void* d_out, int out_size)
{
    const float* x     = (const float*)d_in[0];
    const float* W_dq  = (const float*)d_in[1];
    const float* W_uq  = (const float*)d_in[2];
    const float* q_g   = (const float*)d_in[3];
    const float* q_b   = (const float*)d_in[4];
    const float* W_dkv = (const float*)d_in[5];
    const float* W_ukv = (const float*)d_in[6];
    const float* kv_g  = (const float*)d_in[7];
    const float* kv_b  = (const float*)d_in[8];
    const float* W_o   = (const float*)d_in[9];
    float* out = (float*)d_out;

    float *cq, *ckv, *Qb, *KVb, *AO;
    cudaGetSymbolAddress((void**)&cq,  g_cq);
    cudaGetSymbolAddress((void**)&ckv, g_ckv);
    cudaGetSymbolAddress((void**)&Qb,  g_Q);
    cudaGetSymbolAddress((void**)&KVb, g_KV);
    cudaGetSymbolAddress((void**)&AO,  g_AO);

    // Down-projections: [4096,1024] @ [1024,256]
    mma_gemm<false><<<dim3(PROJ / 128, T_TOK / 128), 256>>>(x, W_dq,  cq,  PROJ, DMODEL);
    mma_gemm<false><<<dim3(PROJ / 128, T_TOK / 128), 256>>>(x, W_dkv, ckv, PROJ, DMODEL);

    // LayerNorms (in-place)
    ln256<<<T_TOK, 256>>>(cq,  q_g,  q_b);
    ln256<<<T_TOK, 256>>>(ckv, kv_g, kv_b);

    // Up-projections
    mma_gemm<false><<<dim3(DMODEL / 128, T_TOK / 128), 256>>>(cq,  W_uq,  Qb,  DMODEL, PROJ);
    mma_gemm<false><<<dim3(2 * DMODEL / 128, T_TOK / 128), 256>>>(ckv, W_ukv, KVb, 2 * DMODEL, PROJ);

    // Attention (fp32, unchanged)
    const size_t smem = 4 * 64 * 68 * sizeof(float);
    cudaFuncSetAttribute(attn_kernel, cudaFuncAttributeMaxDynamicSharedMemorySize, (int)smem);
    attn_kernel<<<dim3(SEQ / 64, HEADS, BATCH), 256, smem>>>(Qb, KVb, AO);

    // Output projection: out = AO @ W_o^T
    mma_gemm<true><<<dim3(DMODEL / 128, T_TOK / 128), 256>>>(AO, W_o, out, DMODEL, DMODEL);
}

// round 6
// speedup vs baseline: 1.9045x; 1.6546x over previous
#include <cuda_runtime.h>
#include <cuda_bf16.h>
#include <math_constants.h>
#include <cstdint>

// Problem constants
#define BATCH   2
#define SEQ     2048
#define T_TOK   4096
#define DMODEL  1024
#define PROJ    256
#define HEADS   16
#define DH      64

// Scratch (device globals: no allocations allowed)
__device__ float g_cq [T_TOK * PROJ];
__device__ float g_ckv[T_TOK * PROJ];
__device__ float g_Q  [T_TOK * DMODEL];
__device__ float g_KV [T_TOK * 2 * DMODEL];
__device__ float g_AO [T_TOK * DMODEL];

// ============================================================================
// Helpers
// ============================================================================
__device__ __forceinline__ void cvt_hilo2(float x, float y, uint32_t& h, uint32_t& l)
{
    __nv_bfloat162 hv = __floats2bfloat162_rn(x, y);   // .x = low half
    float rx = x - __bfloat162float(hv.x);
    float ry = y - __bfloat162float(hv.y);
    __nv_bfloat162 lv = __floats2bfloat162_rn(rx, ry);
    h = *(uint32_t*)&hv;
    l = *(uint32_t*)&lv;
}

__device__ __forceinline__ void mma16816(float* c, uint32_t a0, uint32_t a1,
                                         uint32_t a2, uint32_t a3,
                                         uint32_t b0, uint32_t b1)
{
    asm volatile(
        "mma.sync.aligned.m16n8k16.row.col.f32.bf16.bf16.f32 "
        "{%0,%1,%2,%3}, {%4,%5,%6,%7}, {%8,%9}, {%0,%1,%2,%3};\n"
        : "+f"(c[0]), "+f"(c[1]), "+f"(c[2]), "+f"(c[3])
        : "r"(a0), "r"(a1), "r"(a2), "r"(a3), "r"(b0), "r"(b1));
}

// ============================================================================
// mma_gemm (unchanged from R5): C[M,N](fp32) = A[M,K] @ B, bf16 hi/lo 3-pass.
// ============================================================================
#define PADW 21

__device__ __forceinline__ void stage_rowmajor_mma(
    const float* __restrict__ G, int ldg,
    uint32_t* __restrict__ sh, uint32_t* __restrict__ sl, int tid)
{
#pragma unroll
    for (int i = 0; i < 4; i++) {
        const int f4id = i * 256 + tid;
        const int row = f4id >> 3;
        const int c4  = f4id & 7;
        float4 v = *(const float4*)&G[(size_t)row * ldg + c4 * 4];
        uint32_t h0, l0, h1, l1;
        cvt_hilo2(v.x, v.y, h0, l0);
        cvt_hilo2(v.z, v.w, h1, l1);
        const int w = row * PADW + c4 * 2;
        sh[w] = h0; sh[w + 1] = h1;
        sl[w] = l0; sl[w + 1] = l1;
    }
}

__device__ __forceinline__ void stage_transpose_mma(
    const float* __restrict__ G, int ldg,
    uint32_t* __restrict__ sh, uint32_t* __restrict__ sl, int tid)
{
    __nv_bfloat16* bh = (__nv_bfloat16*)sh;
    __nv_bfloat16* bl = (__nv_bfloat16*)sl;
#pragma unroll
    for (int i = 0; i < 4; i++) {
        const int f4id = i * 256 + tid;
        const int kr = f4id >> 5;
        const int n4 = f4id & 31;
        float4 v = *(const float4*)&G[(size_t)kr * ldg + n4 * 4];
        float vv[4] = {v.x, v.y, v.z, v.w};
#pragma unroll
        for (int j = 0; j < 4; j++) {
            const int n = n4 * 4 + j;
            __nv_bfloat16 h = __float2bfloat16(vv[j]);
            __nv_bfloat16 l = __float2bfloat16(vv[j] - __bfloat162float(h));
            bh[n * (2 * PADW) + kr] = h;
            bl[n * (2 * PADW) + kr] = l;
        }
    }
}

template <bool TRANSB>
__global__ __launch_bounds__(256) void mma_gemm(
    const float* __restrict__ A, const float* __restrict__ B,
    float* __restrict__ C, int N, int K)
{
    __shared__ uint32_t sA[2][128 * PADW];
    __shared__ uint32_t sB[2][128 * PADW];

    const int tid  = threadIdx.x;
    const int warp = tid >> 5, lane = tid & 31;
    const int g = lane >> 2, t = lane & 3;
    const int mi = (warp & 1) * 64;
    const int ni = (warp >> 1) * 32;
    const int bm = blockIdx.y * 128, bn = blockIdx.x * 128;

    float acc[4][4][4] = {};

    const int nchunks = K / 32;
    for (int c = 0; c < nchunks; c++) {
        const int k0 = c * 32;
        __syncthreads();
        stage_rowmajor_mma(A + (size_t)bm * K + k0, K, sA[0], sA[1], tid);
        if (TRANSB)
            stage_rowmajor_mma(B + (size_t)bn * K + k0, K, sB[0], sB[1], tid);
        else
            stage_transpose_mma(B + (size_t)k0 * N + bn, N, sB[0], sB[1], tid);
        __syncthreads();

#pragma unroll
        for (int p = 0; p < 3; p++) {
            const uint32_t* pa = sA[(p == 2) ? 1 : 0];
            const uint32_t* pb = sB[(p == 1) ? 1 : 0];
#pragma unroll
            for (int k2 = 0; k2 < 2; k2++) {
                const int w0 = k2 * 8 + t;
                uint32_t af[4][4];
#pragma unroll
                for (int fm = 0; fm < 4; fm++) {
                    const int r0 = mi + fm * 16 + g;
                    af[fm][0] = pa[r0 * PADW + w0];
                    af[fm][1] = pa[(r0 + 8) * PADW + w0];
                    af[fm][2] = pa[r0 * PADW + w0 + 4];
                    af[fm][3] = pa[(r0 + 8) * PADW + w0 + 4];
                }
                uint32_t bf[4][2];
#pragma unroll
                for (int fn = 0; fn < 4; fn++) {
                    const int n0 = ni + fn * 8 + g;
                    bf[fn][0] = pb[n0 * PADW + w0];
                    bf[fn][1] = pb[n0 * PADW + w0 + 4];
                }
#pragma unroll
                for (int fm = 0; fm < 4; fm++)
#pragma unroll
                    for (int fn = 0; fn < 4; fn++)
                        mma16816(acc[fm][fn], af[fm][0], af[fm][1],
                                 af[fm][2], af[fm][3], bf[fn][0], bf[fn][1]);
            }
        }
    }

#pragma unroll
    for (int fm = 0; fm < 4; fm++) {
        const int row = bm + mi + fm * 16 + g;
#pragma unroll
        for (int fn = 0; fn < 4; fn++) {
            const int col = bn + ni + fn * 8 + t * 2;
            *(float2*)&C[(size_t)row * N + col] =
                make_float2(acc[fm][fn][0], acc[fm][fn][1]);
            *(float2*)&C[(size_t)(row + 8) * N + col] =
                make_float2(acc[fm][fn][2], acc[fm][fn][3]);
        }
    }
}

// ---------------------------------------------------------------------------
// LayerNorm over width=256, one block per row, in-place.
// ---------------------------------------------------------------------------
__global__ __launch_bounds__(256) void ln256(
    float* __restrict__ X, const float* __restrict__ g,
    const float* __restrict__ b)
{
    const int row = blockIdx.x, tid = threadIdx.x;
    float v = X[(size_t)row * 256 + tid];

    __shared__ float red[8];
    float s = v;
#pragma unroll
    for (int m = 16; m > 0; m >>= 1) s += __shfl_xor_sync(0xffffffffu, s, m);
    if ((tid & 31) == 0) red[tid >> 5] = s;
    __syncthreads();
    float tot = 0.f;
#pragma unroll
    for (int i = 0; i < 8; i++) tot += red[i];
    const float mu = tot * (1.0f / 256.0f);
    const float d = v - mu;

    s = d * d;
    __syncthreads();
#pragma unroll
    for (int m = 16; m > 0; m >>= 1) s += __shfl_xor_sync(0xffffffffu, s, m);
    if ((tid & 31) == 0) red[tid >> 5] = s;
    __syncthreads();
    tot = 0.f;
#pragma unroll
    for (int i = 0; i < 8; i++) tot += red[i];
    const float var = tot * (1.0f / 256.0f);

    X[(size_t)row * 256 + tid] = d * rsqrtf(var + 1e-5f) * g[tid] + b[tid];
}

// ============================================================================
// attn_mma: causal flash attention on tensor cores (bf16 hi/lo, 3 passes).
// CTA: 256 threads / 8 warps; q-tile 128 (warp w owns rows w*16..w*16+15),
// k-tile 64. S = (Q/8)K^T via mma; softmax fp32 in registers; P reuses the
// S fragment registers as the A operand of PV (layout identity).
// SMEM: K staged [tok][d] (stride 36 words), V staged transposed [d][tok].
// ============================================================================
#define ASTR 36   // smem row stride in u32 words (conflict-free frag loads)
#define NEG_BIG (-1e30f)

__global__ __launch_bounds__(256) void attn_mma(
    const float* __restrict__ Q, const float* __restrict__ KV,
    float* __restrict__ O)
{
    __shared__ uint32_t Ksh[64 * ASTR], Ksl[64 * ASTR];
    __shared__ uint32_t Vth[64 * ASTR], Vtl[64 * ASTR];

    const int tid = threadIdx.x;
    const int warp = tid >> 5, lane = tid & 31;
    const int g = lane >> 2, t = lane & 3;
    const int qt = blockIdx.x, h = blockIdx.y, b = blockIdx.z;
    const int m0 = warp * 16;                         // row strip in q-tile
    const size_t tokq = (size_t)b * SEQ + (size_t)qt * 128;

    // ---- Q fragments (scaled by 1/8, folded exactly), gmem -> regs once ----
    uint32_t qh[4][4], ql[4][4];
    {
        const float* q0 = &Q[(tokq + m0 + g) * DMODEL + h * DH];
        const float* q1 = q0 + 8 * DMODEL;
#pragma unroll
        for (int kc = 0; kc < 4; kc++) {
            const int c0 = kc * 16 + 2 * t;
            float2 v00 = *(const float2*)(q0 + c0);
            float2 v10 = *(const float2*)(q1 + c0);
            float2 v01 = *(const float2*)(q0 + c0 + 8);
            float2 v11 = *(const float2*)(q1 + c0 + 8);
            cvt_hilo2(v00.x * 0.125f, v00.y * 0.125f, qh[kc][0], ql[kc][0]);
            cvt_hilo2(v10.x * 0.125f, v10.y * 0.125f, qh[kc][1], ql[kc][1]);
            cvt_hilo2(v01.x * 0.125f, v01.y * 0.125f, qh[kc][2], ql[kc][2]);
            cvt_hilo2(v11.x * 0.125f, v11.y * 0.125f, qh[kc][3], ql[kc][3]);
        }
    }

    float oacc[8][4] = {};
    float m_0 = NEG_BIG, m_1 = NEG_BIG, l_0 = 0.f, l_1 = 0.f;

    const int nkt = 2 * qt + 2;
    for (int kt = 0; kt < nkt; kt++) {
        const size_t tokk = (size_t)b * SEQ + (size_t)kt * 64;
        __syncthreads();   // previous tile's fragment reads complete

        // ---- stage K: [tok][d] hi/lo packed words ----
        {
            const int row = tid >> 2;            // 0..63 (token)
            const int c4  = tid & 3;             // 4 float4 across d... need 16
            const float* kr = &KV[(tokk + row) * (2 * DMODEL) + h * DH];
#pragma unroll
            for (int i = 0; i < 4; i++) {
                const int cc = c4 * 4 + i * 16;  // d base (float4)
                float4 v = *(const float4*)(kr + cc);
                uint32_t h0, l0, h1, l1;
                cvt_hilo2(v.x, v.y, h0, l0);
                cvt_hilo2(v.z, v.w, h1, l1);
                const int w = row * ASTR + cc / 2;
                Ksh[w] = h0; Ksh[w + 1] = h1;
                Ksl[w] = l0; Ksl[w + 1] = l1;
            }
        }
        // ---- stage V transposed: Vt[d][tok] ----
        {
            const int d  = tid & 63;
            const int tg = tid >> 6;             // 0..3, tokens tg*16..+15
            const float* vcol = &KV[(tokk + tg * 16) * (2 * DMODEL) + DMODEL + h * DH + d];
#pragma unroll
            for (int w = 0; w < 8; w++) {
                float v0 = vcol[(2 * w) * (2 * DMODEL)];
                float v1 = vcol[(2 * w + 1) * (2 * DMODEL)];
                uint32_t hh, ll;
                cvt_hilo2(v0, v1, hh, ll);
                Vth[d * ASTR + tg * 8 + w] = hh;
                Vtl[d * ASTR + tg * 8 + w] = ll;
            }
        }
        __syncthreads();

        // Warp strip fully masked for this tile? (cols start at kt*64)
        if (kt * 64 > qt * 128 + m0 + 15) continue;

        // ---- S = (Q/8) K^T : 3-pass hi/lo ----
        float s[8][4] = {};
#pragma unroll
        for (int kc = 0; kc < 4; kc++) {
#pragma unroll
            for (int fn = 0; fn < 8; fn++) {
                const int bw = (fn * 8 + g) * ASTR + kc * 8 + t;
                uint32_t bh0 = Ksh[bw], bh1 = Ksh[bw + 4];
                uint32_t bl0 = Ksl[bw], bl1 = Ksl[bw + 4];
                mma16816(s[fn], qh[kc][0], qh[kc][1], qh[kc][2], qh[kc][3], bh0, bh1);
                mma16816(s[fn], qh[kc][0], qh[kc][1], qh[kc][2], qh[kc][3], bl0, bl1);
                mma16816(s[fn], ql[kc][0], ql[kc][1], ql[kc][2], ql[kc][3], bh0, bh1);
            }
        }

        // ---- causal mask (only the diagonal band needs it) ----
        if (kt >= 2 * qt) {
            const int r0 = qt * 128 + m0 + g;
            const int r1 = r0 + 8;
#pragma unroll
            for (int fn = 0; fn < 8; fn++) {
                const int c0 = kt * 64 + fn * 8 + 2 * t;
                if (c0 > r0)     s[fn][0] = NEG_BIG;
                if (c0 + 1 > r0) s[fn][1] = NEG_BIG;
                if (c0 > r1)     s[fn][2] = NEG_BIG;
                if (c0 + 1 > r1) s[fn][3] = NEG_BIG;
            }
        }

        // ---- online softmax (rows g and g+8; quad = 4 lanes of a row) ----
        float mx0 = s[0][0], mx1 = s[0][2];
#pragma unroll
        for (int fn = 0; fn < 8; fn++) {
            mx0 = fmaxf(mx0, fmaxf(s[fn][0], s[fn][1]));
            mx1 = fmaxf(mx1, fmaxf(s[fn][2], s[fn][3]));
        }
        mx0 = fmaxf(mx0, __shfl_xor_sync(0xffffffffu, mx0, 1));
        mx0 = fmaxf(mx0, __shfl_xor_sync(0xffffffffu, mx0, 2));
        mx1 = fmaxf(mx1, __shfl_xor_sync(0xffffffffu, mx1, 1));
        mx1 = fmaxf(mx1, __shfl_xor_sync(0xffffffffu, mx1, 2));

        const float mn0 = fmaxf(m_0, mx0), mn1 = fmaxf(m_1, mx1);
        const float cr0 = __expf(m_0 - mn0), cr1 = __expf(m_1 - mn1);
        m_0 = mn0; m_1 = mn1;

        float sum0 = 0.f, sum1 = 0.f;
#pragma unroll
        for (int fn = 0; fn < 8; fn++) {
            s[fn][0] = __expf(s[fn][0] - mn0);
            s[fn][1] = __expf(s[fn][1] - mn0);
            s[fn][2] = __expf(s[fn][2] - mn1);
            s[fn][3] = __expf(s[fn][3] - mn1);
            sum0 += s[fn][0] + s[fn][1];
            sum1 += s[fn][2] + s[fn][3];
        }
        sum0 += __shfl_xor_sync(0xffffffffu, sum0, 1);
        sum0 += __shfl_xor_sync(0xffffffffu, sum0, 2);
        sum1 += __shfl_xor_sync(0xffffffffu, sum1, 1);
        sum1 += __shfl_xor_sync(0xffffffffu, sum1, 2);
        l_0 = l_0 * cr0 + sum0;
        l_1 = l_1 * cr1 + sum1;

#pragma unroll
        for (int fn = 0; fn < 8; fn++) {
            oacc[fn][0] *= cr0; oacc[fn][1] *= cr0;
            oacc[fn][2] *= cr1; oacc[fn][3] *= cr1;
        }

        // ---- pack P to bf16 hi/lo (fragment registers = PV A operand) ----
        uint32_t ph[8], ph2[8], pl[8], pl2[8];
#pragma unroll
        for (int fn = 0; fn < 8; fn++) {
            cvt_hilo2(s[fn][0], s[fn][1], ph[fn],  pl[fn]);
            cvt_hilo2(s[fn][2], s[fn][3], ph2[fn], pl2[fn]);
        }

        // ---- O += P V : 3-pass hi/lo ----
#pragma unroll
        for (int kc = 0; kc < 4; kc++) {
            const uint32_t ah0 = ph[2 * kc],      ah1 = ph2[2 * kc];
            const uint32_t ah2 = ph[2 * kc + 1],  ah3 = ph2[2 * kc + 1];
            const uint32_t al0 = pl[2 * kc],      al1 = pl2[2 * kc];
            const uint32_t al2 = pl[2 * kc + 1],  al3 = pl2[2 * kc + 1];
#pragma unroll
            for (int fn = 0; fn < 8; fn++) {
                const int bw = (fn * 8 + g) * ASTR + kc * 8 + t;
                uint32_t bh0 = Vth[bw], bh1 = Vth[bw + 4];
                uint32_t bl0 = Vtl[bw], bl1 = Vtl[bw + 4];
                mma16816(oacc[fn], ah0, ah1, ah2, ah3, bh0, bh1);
                mma16816(oacc[fn], ah0, ah1, ah2, ah3, bl0, bl1);
                mma16816(oacc[fn], al0, al1, al2, al3, bh0, bh1);
            }
        }
    }

    // ---- normalize and write out ----
    const float inv0 = 1.0f / l_0, inv1 = 1.0f / l_1;
    const size_t r0 = (tokq + m0 + g) * DMODEL + h * DH;
    const size_t r1 = r0 + 8 * DMODEL;
#pragma unroll
    for (int fn = 0; fn < 8; fn++) {
        const int col = fn * 8 + 2 * t;
        *(float2*)&O[r0 + col] = make_float2(oacc[fn][0] * inv0, oacc[fn][1] * inv0);
        *(float2*)&O[r1 + col] = make_float2(oacc[fn][2] * inv1, oacc[fn][3] * inv1);
    }
}

// ---------------------------------------------------------------------------
// Launch
// ---------------------------------------------------------------------------
extern "C" void kernel_launch(void* const* d_in, const int* in_sizes, int n_in,
                              void* d_out, int out_size)
{
    const float* x     = (const float*)d_in[0];
    const float* W_dq  = (const float*)d_in[1];
    const float* W_uq  = (const float*)d_in[2];
    const float* q_g   = (const float*)d_in[3];
    const float* q_b   = (const float*)d_in[4];
    const float* W_dkv = (const float*)d_in[5];
    const float* W_ukv = (const float*)d_in[6];
    const float* kv_g  = (const float*)d_in[7];
    const float* kv_b  = (const float*)d_in[8];
    const float* W_o   = (const float*)d_in[9];
    float* out = (float*)d_out;

    float *cq, *ckv, *Qb, *KVb, *AO;
    cudaGetSymbolAddress((void**)&cq,  g_cq);
    cudaGetSymbolAddress((void**)&ckv, g_ckv);
    cudaGetSymbolAddress((void**)&Qb,  g_Q);
    cudaGetSymbolAddress((void**)&KVb, g_KV);
    cudaGetSymbolAddress((void**)&AO,  g_AO);

    // Down-projections: [4096,1024] @ [1024,256]
    mma_gemm<false><<<dim3(PROJ / 128, T_TOK / 128), 256>>>(x, W_dq,  cq,  PROJ, DMODEL);
    mma_gemm<false><<<dim3(PROJ / 128, T_TOK / 128), 256>>>(x, W_dkv, ckv, PROJ, DMODEL);

    // LayerNorms (in-place)
    ln256<<<T_TOK, 256>>>(cq,  q_g,  q_b);
    ln256<<<T_TOK, 256>>>(ckv, kv_g, kv_b);

    // Up-projections
    mma_gemm<false><<<dim3(DMODEL / 128, T_TOK / 128), 256>>>(cq,  W_uq,  Qb,  DMODEL, PROJ);
    mma_gemm<false><<<dim3(2 * DMODEL / 128, T_TOK / 128), 256>>>(ckv, W_ukv, KVb, 2 * DMODEL, PROJ);

    // Attention (tensor-core bf16 hi/lo flash attention)
    attn_mma<<<dim3(SEQ / 128, HEADS, BATCH), 256>>>(Qb, KVb, AO);

    // Output projection: out = AO @ W_o^T
    mma_gemm<true><<<dim3(DMODEL / 128, T_TOK / 128), 256>>>(AO, W_o, out, DMODEL, DMODEL);
}

// round 7
// speedup vs baseline: 2.5000x; 1.3127x over previous
#include <cuda_runtime.h>
#include <cuda_bf16.h>
#include <math_constants.h>
#include <cstdint>

// Problem constants
#define BATCH   2
#define SEQ     2048
#define T_TOK   4096
#define DMODEL  1024
#define PROJ    256
#define HEADS   16
#define DH      64

// ---------------------------------------------------------------------------
// Scratch (device globals)
// ---------------------------------------------------------------------------
__device__ uint32_t g_xh  [T_TOK * DMODEL / 2];        // x packed hi
__device__ uint32_t g_xl  [T_TOK * DMODEL / 2];
__device__ uint32_t g_wdqh[PROJ * DMODEL / 2],  g_wdql[PROJ * DMODEL / 2];    // [256][512]
__device__ uint32_t g_wdkh[PROJ * DMODEL / 2],  g_wdkl[PROJ * DMODEL / 2];
__device__ uint32_t g_wuqh[DMODEL * PROJ / 2],  g_wuql[DMODEL * PROJ / 2];    // [1024][128]
__device__ uint32_t g_wukh[2 * DMODEL * PROJ / 2], g_wukl[2 * DMODEL * PROJ / 2]; // [2048][128]
__device__ uint32_t g_woh [DMODEL * DMODEL / 2], g_wol [DMODEL * DMODEL / 2];  // [1024][512]
__device__ float    g_cq  [T_TOK * PROJ];
__device__ float    g_ckv [T_TOK * PROJ];
__device__ uint32_t g_cqph[T_TOK * PROJ / 2],  g_cqpl[T_TOK * PROJ / 2];      // [4096][128]
__device__ uint32_t g_ckph[T_TOK * PROJ / 2],  g_ckpl[T_TOK * PROJ / 2];
__device__ float    g_Q   [T_TOK * DMODEL];
__device__ float    g_KV  [T_TOK * 2 * DMODEL];
__device__ uint32_t g_aoh [T_TOK * DMODEL / 2], g_aol [T_TOK * DMODEL / 2];   // [4096][512]

// ---------------------------------------------------------------------------
// Helpers
// ---------------------------------------------------------------------------
__device__ __forceinline__ void cvt_hilo2(float x, float y, uint32_t& h, uint32_t& l)
{
    __nv_bfloat162 hv = __floats2bfloat162_rn(x, y);   // .x = low half
    float rx = x - __bfloat162float(hv.x);
    float ry = y - __bfloat162float(hv.y);
    __nv_bfloat162 lv = __floats2bfloat162_rn(rx, ry);
    h = *(uint32_t*)&hv;
    l = *(uint32_t*)&lv;
}

__device__ __forceinline__ void mma16816(float* c, uint32_t a0, uint32_t a1,
                                         uint32_t a2, uint32_t a3,
                                         uint32_t b0, uint32_t b1)
{
    asm volatile(
        "mma.sync.aligned.m16n8k16.row.col.f32.bf16.bf16.f32 "
        "{%0,%1,%2,%3}, {%4,%5,%6,%7}, {%8,%9}, {%0,%1,%2,%3};\n"
        : "+f"(c[0]), "+f"(c[1]), "+f"(c[2]), "+f"(c[3])
        : "r"(a0), "r"(a1), "r"(a2), "r"(a3), "r"(b0), "r"(b1));
}

// ---------------------------------------------------------------------------
// Pack kernels (fp32 -> bf16 hi/lo packed u32 words, 2 values per word)
// ---------------------------------------------------------------------------
__global__ __launch_bounds__(256) void pack_hilo(
    const float* __restrict__ X, uint32_t* __restrict__ H,
    uint32_t* __restrict__ L, int nwords)
{
    const int i = blockIdx.x * 256 + threadIdx.x;
    if (i >= nwords) return;
    float2 v = ((const float2*)X)[i];
    uint32_t h, l;
    cvt_hilo2(v.x, v.y, h, l);
    H[i] = h; L[i] = l;
}

// W [K][N] row-major -> H/L [N][K/2] words (transpose + pack along K)
__global__ __launch_bounds__(256) void pack_hilo_t(
    const float* __restrict__ W, uint32_t* __restrict__ H,
    uint32_t* __restrict__ L, int N, int Kw)
{
    const int idx = blockIdx.x * 256 + threadIdx.x;
    if (idx >= N * Kw) return;
    const int kw = idx / N;        // consecutive threads: consecutive n (coalesced reads)
    const int n  = idx - kw * N;
    float a = W[(size_t)(2 * kw) * N + n];
    float b = W[(size_t)(2 * kw + 1) * N + n];
    uint32_t h, l;
    cvt_hilo2(a, b, h, l);
    H[(size_t)n * Kw + kw] = h;
    L[(size_t)n * Kw + kw] = l;
}

// ============================================================================
// gemm_bf: C[M,N](fp32) = (Ah+Al)[M,K] @ (Bh+Bl)^T, operands pre-packed
// hi/lo bf16 words along K. A: [M][Kw], B: [N][Kw]. 3-pass hi/lo MMA.
// Tile 128x128, K-chunk 32 (16 words), 256 threads, reg-double-buffered.
// Optional dual-B: blocks with bx < halfx use set 0, else set 1.
// ============================================================================
#define GSTR 20   // smem row stride in words (16 data + 4 pad; 16B-aligned)

__global__ __launch_bounds__(256) void gemm_bf(
    const uint32_t* __restrict__ Ah, const uint32_t* __restrict__ Al,
    const uint32_t* __restrict__ B0h, const uint32_t* __restrict__ B0l,
    const uint32_t* __restrict__ B1h, const uint32_t* __restrict__ B1l,
    float* __restrict__ C0, float* __restrict__ C1,
    int N, int Kw, int halfx)
{
    __shared__ uint32_t sAh[128 * GSTR], sAl[128 * GSTR];
    __shared__ uint32_t sBh[128 * GSTR], sBl[128 * GSTR];

    const int tid  = threadIdx.x;
    const int warp = tid >> 5, lane = tid & 31;
    const int g = lane >> 2, t = lane & 3;
    const int mi = (warp & 1) * 64;
    const int ni = (warp >> 1) * 32;

    const int bx = blockIdx.x;
    const bool sel0 = bx < halfx;
    const uint32_t* Bh = sel0 ? B0h : B1h;
    const uint32_t* Bl = sel0 ? B0l : B1l;
    float* C = sel0 ? C0 : C1;
    const int bn = (sel0 ? bx : bx - halfx) * 128;
    const int bm = blockIdx.y * 128;

    // per-thread staging slots: idx = i*256+tid -> row = idx>>2, seg = idx&3
    const int r0s = (tid) >> 2, s0s = (tid) & 3;
    const int r1s = (256 + tid) >> 2, s1s = (256 + tid) & 3;

    const uint32_t* pAh = Ah + (size_t)bm * Kw;
    const uint32_t* pAl = Al + (size_t)bm * Kw;
    const uint32_t* pBh = Bh + (size_t)bn * Kw;
    const uint32_t* pBl = Bl + (size_t)bn * Kw;

    uint4 rg[8];
    auto load_chunk = [&](int c) {
        const int kb = c * 16;
        rg[0] = *(const uint4*)&pAh[(size_t)r0s * Kw + kb + s0s * 4];
        rg[1] = *(const uint4*)&pAh[(size_t)r1s * Kw + kb + s1s * 4];
        rg[2] = *(const uint4*)&pAl[(size_t)r0s * Kw + kb + s0s * 4];
        rg[3] = *(const uint4*)&pAl[(size_t)r1s * Kw + kb + s1s * 4];
        rg[4] = *(const uint4*)&pBh[(size_t)r0s * Kw + kb + s0s * 4];
        rg[5] = *(const uint4*)&pBh[(size_t)r1s * Kw + kb + s1s * 4];
        rg[6] = *(const uint4*)&pBl[(size_t)r0s * Kw + kb + s0s * 4];
        rg[7] = *(const uint4*)&pBl[(size_t)r1s * Kw + kb + s1s * 4];
    };
    auto store_chunk = [&]() {
        *(uint4*)&sAh[r0s * GSTR + s0s * 4] = rg[0];
        *(uint4*)&sAh[r1s * GSTR + s1s * 4] = rg[1];
        *(uint4*)&sAl[r0s * GSTR + s0s * 4] = rg[2];
        *(uint4*)&sAl[r1s * GSTR + s1s * 4] = rg[3];
        *(uint4*)&sBh[r0s * GSTR + s0s * 4] = rg[4];
        *(uint4*)&sBh[r1s * GSTR + s1s * 4] = rg[5];
        *(uint4*)&sBl[r0s * GSTR + s0s * 4] = rg[6];
        *(uint4*)&sBl[r1s * GSTR + s1s * 4] = rg[7];
    };

    float acc[4][4][4] = {};

    const int nch = Kw / 16;
    load_chunk(0);
    for (int c = 0; c < nch; c++) {
        __syncthreads();            // previous compute done, smem reusable
        store_chunk();
        __syncthreads();
        if (c + 1 < nch) load_chunk(c + 1);   // LDG latency hidden by MMA below

#pragma unroll
        for (int k2 = 0; k2 < 2; k2++) {
            const int w0 = k2 * 8 + t;
            uint32_t afh[4][4], afl[4][4];
#pragma unroll
            for (int fm = 0; fm < 4; fm++) {
                const int r0 = mi + fm * 16 + g;
                afh[fm][0] = sAh[r0 * GSTR + w0];
                afh[fm][1] = sAh[(r0 + 8) * GSTR + w0];
                afh[fm][2] = sAh[r0 * GSTR + w0 + 4];
                afh[fm][3] = sAh[(r0 + 8) * GSTR + w0 + 4];
                afl[fm][0] = sAl[r0 * GSTR + w0];
                afl[fm][1] = sAl[(r0 + 8) * GSTR + w0];
                afl[fm][2] = sAl[r0 * GSTR + w0 + 4];
                afl[fm][3] = sAl[(r0 + 8) * GSTR + w0 + 4];
            }
            uint32_t bfh[4][2], bfl[4][2];
#pragma unroll
            for (int fn = 0; fn < 4; fn++) {
                const int n0 = ni + fn * 8 + g;
                bfh[fn][0] = sBh[n0 * GSTR + w0];
                bfh[fn][1] = sBh[n0 * GSTR + w0 + 4];
                bfl[fn][0] = sBl[n0 * GSTR + w0];
                bfl[fn][1] = sBl[n0 * GSTR + w0 + 4];
            }
#pragma unroll
            for (int fm = 0; fm < 4; fm++)
#pragma unroll
                for (int fn = 0; fn < 4; fn++) {
                    mma16816(acc[fm][fn], afh[fm][0], afh[fm][1],
                             afh[fm][2], afh[fm][3], bfh[fn][0], bfh[fn][1]);
                    mma16816(acc[fm][fn], afh[fm][0], afh[fm][1],
                             afh[fm][2], afh[fm][3], bfl[fn][0], bfl[fn][1]);
                    mma16816(acc[fm][fn], afl[fm][0], afl[fm][1],
                             afl[fm][2], afl[fm][3], bfh[fn][0], bfh[fn][1]);
                }
        }
    }

#pragma unroll
    for (int fm = 0; fm < 4; fm++) {
        const int row = bm + mi + fm * 16 + g;
#pragma unroll
        for (int fn = 0; fn < 4; fn++) {
            const int col = bn + ni + fn * 8 + t * 2;
            *(float2*)&C[(size_t)row * N + col] =
                make_float2(acc[fm][fn][0], acc[fm][fn][1]);
            *(float2*)&C[(size_t)(row + 8) * N + col] =
                make_float2(acc[fm][fn][2], acc[fm][fn][3]);
        }
    }
}

// ---------------------------------------------------------------------------
// Fused LayerNorm (width 256) + hi/lo pack. Row < T_TOK: cq set, else ckv.
// ---------------------------------------------------------------------------
__global__ __launch_bounds__(256) void ln256_pack(
    const float* __restrict__ X0, const float* __restrict__ X1,
    const float* __restrict__ g0, const float* __restrict__ b0,
    const float* __restrict__ g1, const float* __restrict__ b1,
    uint32_t* __restrict__ H0, uint32_t* __restrict__ L0,
    uint32_t* __restrict__ H1, uint32_t* __restrict__ L1)
{
    const int rr = blockIdx.x;
    const bool first = rr < T_TOK;
    const int row = first ? rr : rr - T_TOK;
    const float* X = first ? X0 : X1;
    const float* gg = first ? g0 : g1;
    const float* bb = first ? b0 : b1;
    uint32_t* H = first ? H0 : H1;
    uint32_t* L = first ? L0 : L1;

    const int tid = threadIdx.x;
    float v = X[(size_t)row * 256 + tid];

    __shared__ float red[8];
    float s = v;
#pragma unroll
    for (int m = 16; m > 0; m >>= 1) s += __shfl_xor_sync(0xffffffffu, s, m);
    if ((tid & 31) == 0) red[tid >> 5] = s;
    __syncthreads();
    float tot = 0.f;
#pragma unroll
    for (int i = 0; i < 8; i++) tot += red[i];
    const float mu = tot * (1.0f / 256.0f);
    const float d = v - mu;

    s = d * d;
    __syncthreads();
#pragma unroll
    for (int m = 16; m > 0; m >>= 1) s += __shfl_xor_sync(0xffffffffu, s, m);
    if ((tid & 31) == 0) red[tid >> 5] = s;
    __syncthreads();
    tot = 0.f;
#pragma unroll
    for (int i = 0; i < 8; i++) tot += red[i];
    const float var = tot * (1.0f / 256.0f);

    const float y = d * rsqrtf(var + 1e-5f) * gg[tid] + bb[tid];
    const float y2 = __shfl_down_sync(0xffffffffu, y, 1);
    if ((tid & 1) == 0) {
        uint32_t h, l;
        cvt_hilo2(y, y2, h, l);
        H[(size_t)row * 128 + (tid >> 1)] = h;
        L[(size_t)row * 128 + (tid >> 1)] = l;
    }
}

// ============================================================================
// attn_mma (R6, unchanged math) — epilogue now writes hi/lo packed AO.
// ============================================================================
#define ASTR 36
#define NEG_BIG (-1e30f)

__global__ __launch_bounds__(256) void attn_mma(
    const float* __restrict__ Q, const float* __restrict__ KV,
    uint32_t* __restrict__ AOh, uint32_t* __restrict__ AOl)
{
    __shared__ uint32_t Ksh[64 * ASTR], Ksl[64 * ASTR];
    __shared__ uint32_t Vth[64 * ASTR], Vtl[64 * ASTR];

    const int tid = threadIdx.x;
    const int warp = tid >> 5, lane = tid & 31;
    const int g = lane >> 2, t = lane & 3;
    const int qt = blockIdx.x, h = blockIdx.y, b = blockIdx.z;
    const int m0 = warp * 16;
    const size_t tokq = (size_t)b * SEQ + (size_t)qt * 128;

    uint32_t qh[4][4], ql[4][4];
    {
        const float* q0 = &Q[(tokq + m0 + g) * DMODEL + h * DH];
        const float* q1 = q0 + 8 * DMODEL;
#pragma unroll
        for (int kc = 0; kc < 4; kc++) {
            const int c0 = kc * 16 + 2 * t;
            float2 v00 = *(const float2*)(q0 + c0);
            float2 v10 = *(const float2*)(q1 + c0);
            float2 v01 = *(const float2*)(q0 + c0 + 8);
            float2 v11 = *(const float2*)(q1 + c0 + 8);
            cvt_hilo2(v00.x * 0.125f, v00.y * 0.125f, qh[kc][0], ql[kc][0]);
            cvt_hilo2(v10.x * 0.125f, v10.y * 0.125f, qh[kc][1], ql[kc][1]);
            cvt_hilo2(v01.x * 0.125f, v01.y * 0.125f, qh[kc][2], ql[kc][2]);
            cvt_hilo2(v11.x * 0.125f, v11.y * 0.125f, qh[kc][3], ql[kc][3]);
        }
    }

    float oacc[8][4] = {};
    float m_0 = NEG_BIG, m_1 = NEG_BIG, l_0 = 0.f, l_1 = 0.f;

    const int nkt = 2 * qt + 2;
    for (int kt = 0; kt < nkt; kt++) {
        const size_t tokk = (size_t)b * SEQ + (size_t)kt * 64;
        __syncthreads();

        {
            const int row = tid >> 2;
            const int c4  = tid & 3;
            const float* kr = &KV[(tokk + row) * (2 * DMODEL) + h * DH];
#pragma unroll
            for (int i = 0; i < 4; i++) {
                const int cc = c4 * 4 + i * 16;
                float4 v = *(const float4*)(kr + cc);
                uint32_t h0, l0, h1, l1;
                cvt_hilo2(v.x, v.y, h0, l0);
                cvt_hilo2(v.z, v.w, h1, l1);
                const int w = row * ASTR + cc / 2;
                Ksh[w] = h0; Ksh[w + 1] = h1;
                Ksl[w] = l0; Ksl[w + 1] = l1;
            }
        }
        {
            const int d  = tid & 63;
            const int tg = tid >> 6;
            const float* vcol = &KV[(tokk + tg * 16) * (2 * DMODEL) + DMODEL + h * DH + d];
#pragma unroll
            for (int w = 0; w < 8; w++) {
                float v0 = vcol[(2 * w) * (2 * DMODEL)];
                float v1 = vcol[(2 * w + 1) * (2 * DMODEL)];
                uint32_t hh, ll;
                cvt_hilo2(v0, v1, hh, ll);
                Vth[d * ASTR + tg * 8 + w] = hh;
                Vtl[d * ASTR + tg * 8 + w] = ll;
            }
        }
        __syncthreads();

        if (kt * 64 > qt * 128 + m0 + 15) continue;

        float s[8][4] = {};
#pragma unroll
        for (int kc = 0; kc < 4; kc++) {
#pragma unroll
            for (int fn = 0; fn < 8; fn++) {
                const int bw = (fn * 8 + g) * ASTR + kc * 8 + t;
                uint32_t bh0 = Ksh[bw], bh1 = Ksh[bw + 4];
                uint32_t bl0 = Ksl[bw], bl1 = Ksl[bw + 4];
                mma16816(s[fn], qh[kc][0], qh[kc][1], qh[kc][2], qh[kc][3], bh0, bh1);
                mma16816(s[fn], qh[kc][0], qh[kc][1], qh[kc][2], qh[kc][3], bl0, bl1);
                mma16816(s[fn], ql[kc][0], ql[kc][1], ql[kc][2], ql[kc][3], bh0, bh1);
            }
        }

        if (kt >= 2 * qt) {
            const int r0 = qt * 128 + m0 + g;
            const int r1 = r0 + 8;
#pragma unroll
            for (int fn = 0; fn < 8; fn++) {
                const int c0 = kt * 64 + fn * 8 + 2 * t;
                if (c0 > r0)     s[fn][0] = NEG_BIG;
                if (c0 + 1 > r0) s[fn][1] = NEG_BIG;
                if (c0 > r1)     s[fn][2] = NEG_BIG;
                if (c0 + 1 > r1) s[fn][3] = NEG_BIG;
            }
        }

        float mx0 = s[0][0], mx1 = s[0][2];
#pragma unroll
        for (int fn = 0; fn < 8; fn++) {
            mx0 = fmaxf(mx0, fmaxf(s[fn][0], s[fn][1]));
            mx1 = fmaxf(mx1, fmaxf(s[fn][2], s[fn][3]));
        }
        mx0 = fmaxf(mx0, __shfl_xor_sync(0xffffffffu, mx0, 1));
        mx0 = fmaxf(mx0, __shfl_xor_sync(0xffffffffu, mx0, 2));
        mx1 = fmaxf(mx1, __shfl_xor_sync(0xffffffffu, mx1, 1));
        mx1 = fmaxf(mx1, __shfl_xor_sync(0xffffffffu, mx1, 2));

        const float mn0 = fmaxf(m_0, mx0), mn1 = fmaxf(m_1, mx1);
        const float cr0 = __expf(m_0 - mn0), cr1 = __expf(m_1 - mn1);
        m_0 = mn0; m_1 = mn1;

        float sum0 = 0.f, sum1 = 0.f;
#pragma unroll
        for (int fn = 0; fn < 8; fn++) {
            s[fn][0] = __expf(s[fn][0] - mn0);
            s[fn][1] = __expf(s[fn][1] - mn0);
            s[fn][2] = __expf(s[fn][2] - mn1);
            s[fn][3] = __expf(s[fn][3] - mn1);
            sum0 += s[fn][0] + s[fn][1];
            sum1 += s[fn][2] + s[fn][3];
        }
        sum0 += __shfl_xor_sync(0xffffffffu, sum0, 1);
        sum0 += __shfl_xor_sync(0xffffffffu, sum0, 2);
        sum1 += __shfl_xor_sync(0xffffffffu, sum1, 1);
        sum1 += __shfl_xor_sync(0xffffffffu, sum1, 2);
        l_0 = l_0 * cr0 + sum0;
        l_1 = l_1 * cr1 + sum1;

#pragma unroll
        for (int fn = 0; fn < 8; fn++) {
            oacc[fn][0] *= cr0; oacc[fn][1] *= cr0;
            oacc[fn][2] *= cr1; oacc[fn][3] *= cr1;
        }

        uint32_t ph[8], ph2[8], pl[8], pl2[8];
#pragma unroll
        for (int fn = 0; fn < 8; fn++) {
            cvt_hilo2(s[fn][0], s[fn][1], ph[fn],  pl[fn]);
            cvt_hilo2(s[fn][2], s[fn][3], ph2[fn], pl2[fn]);
        }

#pragma unroll
        for (int kc = 0; kc < 4; kc++) {
            const uint32_t ah0 = ph[2 * kc],      ah1 = ph2[2 * kc];
            const uint32_t ah2 = ph[2 * kc + 1],  ah3 = ph2[2 * kc + 1];
            const uint32_t al0 = pl[2 * kc],      al1 = pl2[2 * kc];
            const uint32_t al2 = pl[2 * kc + 1],  al3 = pl2[2 * kc + 1];
#pragma unroll
            for (int fn = 0; fn < 8; fn++) {
                const int bw = (fn * 8 + g) * ASTR + kc * 8 + t;
                uint32_t bh0 = Vth[bw], bh1 = Vth[bw + 4];
                uint32_t bl0 = Vtl[bw], bl1 = Vtl[bw + 4];
                mma16816(oacc[fn], ah0, ah1, ah2, ah3, bh0, bh1);
                mma16816(oacc[fn], ah0, ah1, ah2, ah3, bl0, bl1);
                mma16816(oacc[fn], al0, al1, al2, al3, bh0, bh1);
            }
        }
    }

    // ---- normalize + write hi/lo packed AO: word = (col, col+1) pair ----
    const float inv0 = 1.0f / l_0, inv1 = 1.0f / l_1;
    const size_t w0 = (tokq + m0 + g) * (DMODEL / 2) + h * (DH / 2);
    const size_t w1 = w0 + 8 * (DMODEL / 2);
#pragma unroll
    for (int fn = 0; fn < 8; fn++) {
        const int wi = fn * 4 + t;
        uint32_t hh, ll;
        cvt_hilo2(oacc[fn][0] * inv0, oacc[fn][1] * inv0, hh, ll);
        AOh[w0 + wi] = hh; AOl[w0 + wi] = ll;
        cvt_hilo2(oacc[fn][2] * inv1, oacc[fn][3] * inv1, hh, ll);
        AOh[w1 + wi] = hh; AOl[w1 + wi] = ll;
    }
}

// ---------------------------------------------------------------------------
// Launch
// ---------------------------------------------------------------------------
extern "C" void kernel_launch(void* const* d_in, const int* in_sizes, int n_in,
                              void* d_out, int out_size)
{
    const float* x     = (const float*)d_in[0];
    const float* W_dq  = (const float*)d_in[1];
    const float* W_uq  = (const float*)d_in[2];
    const float* q_g   = (const float*)d_in[3];
    const float* q_b   = (const float*)d_in[4];
    const float* W_dkv = (const float*)d_in[5];
    const float* W_ukv = (const float*)d_in[6];
    const float* kv_g  = (const float*)d_in[7];
    const float* kv_b  = (const float*)d_in[8];
    const float* W_o   = (const float*)d_in[9];
    float* out = (float*)d_out;

    uint32_t *xh, *xl, *wdqh, *wdql, *wdkh, *wdkl, *wuqh, *wuql, *wukh, *wukl, *woh, *wol;
    uint32_t *cqph, *cqpl, *ckph, *ckpl, *aoh, *aol;
    float *cq, *ckv, *Qb, *KVb;
    cudaGetSymbolAddress((void**)&xh,   g_xh);   cudaGetSymbolAddress((void**)&xl,   g_xl);
    cudaGetSymbolAddress((void**)&wdqh, g_wdqh); cudaGetSymbolAddress((void**)&wdql, g_wdql);
    cudaGetSymbolAddress((void**)&wdkh, g_wdkh); cudaGetSymbolAddress((void**)&wdkl, g_wdkl);
    cudaGetSymbolAddress((void**)&wuqh, g_wuqh); cudaGetSymbolAddress((void**)&wuql, g_wuql);
    cudaGetSymbolAddress((void**)&wukh, g_wukh); cudaGetSymbolAddress((void**)&wukl, g_wukl);
    cudaGetSymbolAddress((void**)&woh,  g_woh);  cudaGetSymbolAddress((void**)&wol,  g_wol);
    cudaGetSymbolAddress((void**)&cq,   g_cq);   cudaGetSymbolAddress((void**)&ckv,  g_ckv);
    cudaGetSymbolAddress((void**)&cqph, g_cqph); cudaGetSymbolAddress((void**)&cqpl, g_cqpl);
    cudaGetSymbolAddress((void**)&ckph, g_ckph); cudaGetSymbolAddress((void**)&ckpl, g_ckpl);
    cudaGetSymbolAddress((void**)&Qb,   g_Q);    cudaGetSymbolAddress((void**)&KVb,  g_KV);
    cudaGetSymbolAddress((void**)&aoh,  g_aoh);  cudaGetSymbolAddress((void**)&aol,  g_aol);

    // ---- pack inputs ----
    pack_hilo<<<(T_TOK * DMODEL / 2 + 255) / 256, 256>>>(x, xh, xl, T_TOK * DMODEL / 2);
    pack_hilo_t<<<(PROJ * (DMODEL / 2) + 255) / 256, 256>>>(W_dq,  wdqh, wdql, PROJ, DMODEL / 2);
    pack_hilo_t<<<(PROJ * (DMODEL / 2) + 255) / 256, 256>>>(W_dkv, wdkh, wdkl, PROJ, DMODEL / 2);
    pack_hilo_t<<<(DMODEL * (PROJ / 2) + 255) / 256, 256>>>(W_uq,  wuqh, wuql, DMODEL, PROJ / 2);
    pack_hilo_t<<<(2 * DMODEL * (PROJ / 2) + 255) / 256, 256>>>(W_ukv, wukh, wukl, 2 * DMODEL, PROJ / 2);
    pack_hilo<<<(DMODEL * DMODEL / 2 + 255) / 256, 256>>>(W_o, woh, wol, DMODEL * DMODEL / 2);

    // ---- fused down-projections: cq | ckv ----
    gemm_bf<<<dim3(4, T_TOK / 128), 256>>>(xh, xl, wdqh, wdql, wdkh, wdkl,
                                           cq, ckv, PROJ, DMODEL / 2, 2);

    // ---- fused LayerNorm + pack ----
    ln256_pack<<<2 * T_TOK, 256>>>(cq, ckv, q_g, q_b, kv_g, kv_b,
                                   cqph, cqpl, ckph, ckpl);

    // ---- up-projections ----
    gemm_bf<<<dim3(DMODEL / 128, T_TOK / 128), 256>>>(cqph, cqpl, wuqh, wuql, wuqh, wuql,
                                                      Qb, Qb, DMODEL, PROJ / 2, DMODEL / 128);
    gemm_bf<<<dim3(2 * DMODEL / 128, T_TOK / 128), 256>>>(ckph, ckpl, wukh, wukl, wukh, wukl,
                                                          KVb, KVb, 2 * DMODEL, PROJ / 2, 2 * DMODEL / 128);

    // ---- attention (writes packed AO) ----
    attn_mma<<<dim3(SEQ / 128, HEADS, BATCH), 256>>>(Qb, KVb, aoh, aol);

    // ---- output projection: out = AO @ W_o^T ----
    gemm_bf<<<dim3(DMODEL / 128, T_TOK / 128), 256>>>(aoh, aol, woh, wol, woh, wol,
                                                      out, out, DMODEL, DMODEL / 2, DMODEL / 128);
}

// round 10
// speedup vs baseline: 2.5750x; 1.0300x over previous
#include <cuda_runtime.h>
#include <cuda_bf16.h>
#include <math_constants.h>
#include <cstdint>

// Problem constants
#define BATCH   2
#define SEQ     2048
#define T_TOK   4096
#define DMODEL  1024
#define PROJ    256
#define HEADS   16
#define DH      64

// ---------------------------------------------------------------------------
// Scratch (device globals)
// ---------------------------------------------------------------------------
__device__ uint32_t g_xh  [T_TOK * DMODEL / 2];
__device__ uint32_t g_xl  [T_TOK * DMODEL / 2];
__device__ uint32_t g_wdqh[PROJ * DMODEL / 2],  g_wdql[PROJ * DMODEL / 2];
__device__ uint32_t g_wdkh[PROJ * DMODEL / 2],  g_wdkl[PROJ * DMODEL / 2];
__device__ uint32_t g_wuqh[DMODEL * PROJ / 2],  g_wuql[DMODEL * PROJ / 2];
__device__ uint32_t g_wukh[2 * DMODEL * PROJ / 2], g_wukl[2 * DMODEL * PROJ / 2];
__device__ uint32_t g_woh [DMODEL * DMODEL / 2], g_wol [DMODEL * DMODEL / 2];
__device__ float    g_cq  [T_TOK * PROJ];
__device__ float    g_ckv [T_TOK * PROJ];
__device__ uint32_t g_cqph[T_TOK * PROJ / 2],  g_cqpl[T_TOK * PROJ / 2];
__device__ uint32_t g_ckph[T_TOK * PROJ / 2],  g_ckpl[T_TOK * PROJ / 2];
__device__ float    g_Q   [T_TOK * DMODEL];
__device__ float    g_KV  [T_TOK * 2 * DMODEL];
__device__ uint32_t g_aoh [T_TOK * DMODEL / 2], g_aol [T_TOK * DMODEL / 2];

// ---------------------------------------------------------------------------
// Helpers
// ---------------------------------------------------------------------------
__device__ __forceinline__ void cvt_hilo2(float x, float y, uint32_t& h, uint32_t& l)
{
    __nv_bfloat162 hv = __floats2bfloat162_rn(x, y);   // .x = low half
    float rx = x - __bfloat162float(hv.x);
    float ry = y - __bfloat162float(hv.y);
    __nv_bfloat162 lv = __floats2bfloat162_rn(rx, ry);
    h = *(uint32_t*)&hv;
    l = *(uint32_t*)&lv;
}

__device__ __forceinline__ void mma16816(float* c, uint32_t a0, uint32_t a1,
                                         uint32_t a2, uint32_t a3,
                                         uint32_t b0, uint32_t b1)
{
    asm volatile(
        "mma.sync.aligned.m16n8k16.row.col.f32.bf16.bf16.f32 "
        "{%0,%1,%2,%3}, {%4,%5,%6,%7}, {%8,%9}, {%0,%1,%2,%3};\n"
        : "+f"(c[0]), "+f"(c[1]), "+f"(c[2]), "+f"(c[3])
        : "r"(a0), "r"(a1), "r"(a2), "r"(a3), "r"(b0), "r"(b1));
}

__device__ __forceinline__ void ldsm_x4(uint32_t& r0, uint32_t& r1,
                                        uint32_t& r2, uint32_t& r3, uint32_t addr)
{
    asm volatile("ldmatrix.sync.aligned.m8n8.x4.shared.b16 {%0,%1,%2,%3}, [%4];"
                 : "=r"(r0), "=r"(r1), "=r"(r2), "=r"(r3) : "r"(addr));
}

__device__ __forceinline__ uint32_t smem_addr(const void* p)
{
    return (uint32_t)__cvta_generic_to_shared(p);
}

// ---------------------------------------------------------------------------
// Pack kernels
// ---------------------------------------------------------------------------
__global__ __launch_bounds__(256) void pack_hilo(
    const float* __restrict__ X, uint32_t* __restrict__ H,
    uint32_t* __restrict__ L, int nwords)
{
    const int i = blockIdx.x * 256 + threadIdx.x;
    if (i >= nwords) return;
    float2 v = ((const float2*)X)[i];
    uint32_t h, l;
    cvt_hilo2(v.x, v.y, h, l);
    H[i] = h; L[i] = l;
}

// W [K][N] row-major -> H/L [N][K/2] words (transpose + pack along K)
__global__ __launch_bounds__(256) void pack_hilo_t(
    const float* __restrict__ W, uint32_t* __restrict__ H,
    uint32_t* __restrict__ L, int N, int Kw)
{
    const int idx = blockIdx.x * 256 + threadIdx.x;
    if (idx >= N * Kw) return;
    const int kw = idx / N;
    const int n  = idx - kw * N;
    float a = W[(size_t)(2 * kw) * N + n];
    float b = W[(size_t)(2 * kw + 1) * N + n];
    uint32_t h, l;
    cvt_hilo2(a, b, h, l);
    H[(size_t)n * Kw + kw] = h;
    L[(size_t)n * Kw + kw] = l;
}

// ============================================================================
// gemm_bf: C = (Ah+Al)[M,K] @ (Bh+Bl)^T, pre-packed hi/lo words along K.
// Tile 128x128, K-chunk 32 (16 words), 256 threads. Fragment loads: ldmatrix.
// ============================================================================
#define GSTR 20

__global__ __launch_bounds__(256) void gemm_bf(
    const uint32_t* __restrict__ Ah, const uint32_t* __restrict__ Al,
    const uint32_t* __restrict__ B0h, const uint32_t* __restrict__ B0l,
    const uint32_t* __restrict__ B1h, const uint32_t* __restrict__ B1l,
    float* __restrict__ C0, float* __restrict__ C1,
    int N, int Kw, int halfx)
{
    __shared__ uint32_t sAh[128 * GSTR], sAl[128 * GSTR];
    __shared__ uint32_t sBh[128 * GSTR], sBl[128 * GSTR];

    const int tid  = threadIdx.x;
    const int warp = tid >> 5, lane = tid & 31;
    const int g = lane >> 2, t = lane & 3;
    const int mi = (warp & 1) * 64;
    const int ni = (warp >> 1) * 32;

    const int bx = blockIdx.x;
    const bool sel0 = bx < halfx;
    const uint32_t* Bh = sel0 ? B0h : B1h;
    const uint32_t* Bl = sel0 ? B0l : B1l;
    float* C = sel0 ? C0 : C1;
    const int bn = (sel0 ? bx : bx - halfx) * 128;
    const int bm = blockIdx.y * 128;

    const int r0s = tid >> 2, s0s = tid & 3;
    const int r1s = (256 + tid) >> 2, s1s = (256 + tid) & 3;

    const uint32_t* pAh = Ah + (size_t)bm * Kw;
    const uint32_t* pAl = Al + (size_t)bm * Kw;
    const uint32_t* pBh = Bh + (size_t)bn * Kw;
    const uint32_t* pBl = Bl + (size_t)bn * Kw;

    // ldmatrix per-lane base offsets (bytes)
    const int rowA = mi + (lane & 15);
    const int colA = (lane >> 4) * 4;
    const uint32_t offA = (uint32_t)(rowA * GSTR + colA) * 4u;
    const int rowB = ni + (lane & 7) + ((lane >> 4) * 8);
    const int colB = ((lane >> 3) & 1) * 4;
    const uint32_t offB = (uint32_t)(rowB * GSTR + colB) * 4u;
    const uint32_t aAh = smem_addr(sAh) + offA, aAl = smem_addr(sAl) + offA;
    const uint32_t aBh = smem_addr(sBh) + offB, aBl = smem_addr(sBl) + offB;

    uint4 rg[8];
    auto load_chunk = [&](int c) {
        const int kb = c * 16;
        rg[0] = *(const uint4*)&pAh[(size_t)r0s * Kw + kb + s0s * 4];
        rg[1] = *(const uint4*)&pAh[(size_t)r1s * Kw + kb + s1s * 4];
        rg[2] = *(const uint4*)&pAl[(size_t)r0s * Kw + kb + s0s * 4];
        rg[3] = *(const uint4*)&pAl[(size_t)r1s * Kw + kb + s1s * 4];
        rg[4] = *(const uint4*)&pBh[(size_t)r0s * Kw + kb + s0s * 4];
        rg[5] = *(const uint4*)&pBh[(size_t)r1s * Kw + kb + s1s * 4];
        rg[6] = *(const uint4*)&pBl[(size_t)r0s * Kw + kb + s0s * 4];
        rg[7] = *(const uint4*)&pBl[(size_t)r1s * Kw + kb + s1s * 4];
    };
    auto store_chunk = [&]() {
        *(uint4*)&sAh[r0s * GSTR + s0s * 4] = rg[0];
        *(uint4*)&sAh[r1s * GSTR + s1s * 4] = rg[1];
        *(uint4*)&sAl[r0s * GSTR + s0s * 4] = rg[2];
        *(uint4*)&sAl[r1s * GSTR + s1s * 4] = rg[3];
        *(uint4*)&sBh[r0s * GSTR + s0s * 4] = rg[4];
        *(uint4*)&sBh[r1s * GSTR + s1s * 4] = rg[5];
        *(uint4*)&sBl[r0s * GSTR + s0s * 4] = rg[6];
        *(uint4*)&sBl[r1s * GSTR + s1s * 4] = rg[7];
    };

    float acc[4][4][4] = {};

    const int nch = Kw / 16;
    load_chunk(0);
    for (int c = 0; c < nch; c++) {
        __syncthreads();
        store_chunk();
        __syncthreads();
        if (c + 1 < nch) load_chunk(c + 1);

#pragma unroll
        for (int k2 = 0; k2 < 2; k2++) {
            const uint32_t koff = (uint32_t)(k2 * 8) * 4u;
            uint32_t afh[4][4], afl[4][4];
#pragma unroll
            for (int fm = 0; fm < 4; fm++) {
                const uint32_t fo = (uint32_t)(fm * 16 * GSTR) * 4u + koff;
                ldsm_x4(afh[fm][0], afh[fm][1], afh[fm][2], afh[fm][3], aAh + fo);
                ldsm_x4(afl[fm][0], afl[fm][1], afl[fm][2], afl[fm][3], aAl + fo);
            }
            uint32_t bfh[4][2], bfl[4][2];
#pragma unroll
            for (int fnp = 0; fnp < 2; fnp++) {
                const uint32_t fo = (uint32_t)(fnp * 16 * GSTR) * 4u + koff;
                ldsm_x4(bfh[2 * fnp][0], bfh[2 * fnp][1],
                        bfh[2 * fnp + 1][0], bfh[2 * fnp + 1][1], aBh + fo);
                ldsm_x4(bfl[2 * fnp][0], bfl[2 * fnp][1],
                        bfl[2 * fnp + 1][0], bfl[2 * fnp + 1][1], aBl + fo);
            }
#pragma unroll
            for (int fm = 0; fm < 4; fm++)
#pragma unroll
                for (int fn = 0; fn < 4; fn++) {
                    mma16816(acc[fm][fn], afh[fm][0], afh[fm][1],
                             afh[fm][2], afh[fm][3], bfh[fn][0], bfh[fn][1]);
                    mma16816(acc[fm][fn], afh[fm][0], afh[fm][1],
                             afh[fm][2], afh[fm][3], bfl[fn][0], bfl[fn][1]);
                    mma16816(acc[fm][fn], afl[fm][0], afl[fm][1],
                             afl[fm][2], afl[fm][3], bfh[fn][0], bfh[fn][1]);
                }
        }
    }

#pragma unroll
    for (int fm = 0; fm < 4; fm++) {
        const int row = bm + mi + fm * 16 + g;
#pragma unroll
        for (int fn = 0; fn < 4; fn++) {
            const int col = bn + ni + fn * 8 + t * 2;
            *(float2*)&C[(size_t)row * N + col] =
                make_float2(acc[fm][fn][0], acc[fm][fn][1]);
            *(float2*)&C[(size_t)(row + 8) * N + col] =
                make_float2(acc[fm][fn][2], acc[fm][fn][3]);
        }
    }
}

// ---------------------------------------------------------------------------
// Fused LayerNorm (width 256) + hi/lo pack.
// ---------------------------------------------------------------------------
__global__ __launch_bounds__(256) void ln256_pack(
    const float* __restrict__ X0, const float* __restrict__ X1,
    const float* __restrict__ g0, const float* __restrict__ b0,
    const float* __restrict__ g1, const float* __restrict__ b1,
    uint32_t* __restrict__ H0, uint32_t* __restrict__ L0,
    uint32_t* __restrict__ H1, uint32_t* __restrict__ L1)
{
    const int rr = blockIdx.x;
    const bool first = rr < T_TOK;
    const int row = first ? rr : rr - T_TOK;
    const float* X = first ? X0 : X1;
    const float* gg = first ? g0 : g1;
    const float* bb = first ? b0 : b1;
    uint32_t* H = first ? H0 : H1;
    uint32_t* L = first ? L0 : L1;

    const int tid = threadIdx.x;
    float v = X[(size_t)row * 256 + tid];

    __shared__ float red[8];
    float s = v;
#pragma unroll
    for (int m = 16; m > 0; m >>= 1) s += __shfl_xor_sync(0xffffffffu, s, m);
    if ((tid & 31) == 0) red[tid >> 5] = s;
    __syncthreads();
    float tot = 0.f;
#pragma unroll
    for (int i = 0; i < 8; i++) tot += red[i];
    const float mu = tot * (1.0f / 256.0f);
    const float d = v - mu;

    s = d * d;
    __syncthreads();
#pragma unroll
    for (int m = 16; m > 0; m >>= 1) s += __shfl_xor_sync(0xffffffffu, s, m);
    if ((tid & 31) == 0) red[tid >> 5] = s;
    __syncthreads();
    tot = 0.f;
#pragma unroll
    for (int i = 0; i < 8; i++) tot += red[i];
    const float var = tot * (1.0f / 256.0f);

    const float y = d * rsqrtf(var + 1e-5f) * gg[tid] + bb[tid];
    const float y2 = __shfl_down_sync(0xffffffffu, y, 1);
    if ((tid & 1) == 0) {
        uint32_t h, l;
        cvt_hilo2(y, y2, h, l);
        H[(size_t)row * 128 + (tid >> 1)] = h;
        L[(size_t)row * 128 + (tid >> 1)] = l;
    }
}

// ============================================================================
// attn_mma — fragment loads via ldmatrix; math unchanged from R6/R7.
// ============================================================================
#define ASTR 36
#define NEG_BIG (-1e30f)

__global__ __launch_bounds__(256) void attn_mma(
    const float* __restrict__ Q, const float* __restrict__ KV,
    uint32_t* __restrict__ AOh, uint32_t* __restrict__ AOl)
{
    __shared__ uint32_t Ksh[64 * ASTR], Ksl[64 * ASTR];
    __shared__ uint32_t Vth[64 * ASTR], Vtl[64 * ASTR];

    const int tid = threadIdx.x;
    const int warp = tid >> 5, lane = tid & 31;
    const int g = lane >> 2, t = lane & 3;
    const int qt = blockIdx.x, h = blockIdx.y, b = blockIdx.z;
    const int m0 = warp * 16;
    const size_t tokq = (size_t)b * SEQ + (size_t)qt * 128;

    // ldmatrix lane base offset for B-type fragments (K and Vt tiles)
    const int rowF = (lane & 7) + ((lane >> 4) * 8);
    const int colF = ((lane >> 3) & 1) * 4;
    const uint32_t offF = (uint32_t)(rowF * ASTR + colF) * 4u;
    const uint32_t aKh = smem_addr(Ksh) + offF, aKl = smem_addr(Ksl) + offF;
    const uint32_t aVh = smem_addr(Vth) + offF, aVl = smem_addr(Vtl) + offF;

    uint32_t qh[4][4], ql[4][4];
    {
        const float* q0 = &Q[(tokq + m0 + g) * DMODEL + h * DH];
        const float* q1 = q0 + 8 * DMODEL;
#pragma unroll
        for (int kc = 0; kc < 4; kc++) {
            const int c0 = kc * 16 + 2 * t;
            float2 v00 = *(const float2*)(q0 + c0);
            float2 v10 = *(const float2*)(q1 + c0);
            float2 v01 = *(const float2*)(q0 + c0 + 8);
            float2 v11 = *(const float2*)(q1 + c0 + 8);
            cvt_hilo2(v00.x * 0.125f, v00.y * 0.125f, qh[kc][0], ql[kc][0]);
            cvt_hilo2(v10.x * 0.125f, v10.y * 0.125f, qh[kc][1], ql[kc][1]);
            cvt_hilo2(v01.x * 0.125f, v01.y * 0.125f, qh[kc][2], ql[kc][2]);
            cvt_hilo2(v11.x * 0.125f, v11.y * 0.125f, qh[kc][3], ql[kc][3]);
        }
    }

    float oacc[8][4] = {};
    float m_0 = NEG_BIG, m_1 = NEG_BIG, l_0 = 0.f, l_1 = 0.f;

    const int nkt = 2 * qt + 2;
    for (int kt = 0; kt < nkt; kt++) {
        const size_t tokk = (size_t)b * SEQ + (size_t)kt * 64;
        __syncthreads();

        {
            const int row = tid >> 2;
            const int c4  = tid & 3;
            const float* kr = &KV[(tokk + row) * (2 * DMODEL) + h * DH];
#pragma unroll
            for (int i = 0; i < 4; i++) {
                const int cc = c4 * 4 + i * 16;
                float4 v = *(const float4*)(kr + cc);
                uint32_t h0, l0, h1, l1;
                cvt_hilo2(v.x, v.y, h0, l0);
                cvt_hilo2(v.z, v.w, h1, l1);
                const int w = row * ASTR + cc / 2;
                Ksh[w] = h0; Ksh[w + 1] = h1;
                Ksl[w] = l0; Ksl[w + 1] = l1;
            }
        }
        {
            const int d  = tid & 63;
            const int tg = tid >> 6;
            const float* vcol = &KV[(tokk + tg * 16) * (2 * DMODEL) + DMODEL + h * DH + d];
#pragma unroll
            for (int w = 0; w < 8; w++) {
                float v0 = vcol[(2 * w) * (2 * DMODEL)];
                float v1 = vcol[(2 * w + 1) * (2 * DMODEL)];
                uint32_t hh, ll;
                cvt_hilo2(v0, v1, hh, ll);
                Vth[d * ASTR + tg * 8 + w] = hh;
                Vtl[d * ASTR + tg * 8 + w] = ll;
            }
        }
        __syncthreads();

        if (kt * 64 > qt * 128 + m0 + 15) continue;

        // ---- S = (Q/8) K^T : 3-pass hi/lo, ldmatrix fragment loads ----
        float s[8][4] = {};
#pragma unroll
        for (int kc = 0; kc < 4; kc++) {
            const uint32_t kcoff = (uint32_t)(kc * 8) * 4u;
#pragma unroll
            for (int fnp = 0; fnp < 4; fnp++) {
                const uint32_t fo = (uint32_t)(fnp * 16 * ASTR) * 4u + kcoff;
                uint32_t h00, h01, h10, h11, l00, l01, l10, l11;
                ldsm_x4(h00, h01, h10, h11, aKh + fo);
                ldsm_x4(l00, l01, l10, l11, aKl + fo);
                float* sa = s[2 * fnp];
                float* sb = s[2 * fnp + 1];
                mma16816(sa, qh[kc][0], qh[kc][1], qh[kc][2], qh[kc][3], h00, h01);
                mma16816(sa, qh[kc][0], qh[kc][1], qh[kc][2], qh[kc][3], l00, l01);
                mma16816(sa, ql[kc][0], ql[kc][1], ql[kc][2], ql[kc][3], h00, h01);
                mma16816(sb, qh[kc][0], qh[kc][1], qh[kc][2], qh[kc][3], h10, h11);
                mma16816(sb, qh[kc][0], qh[kc][1], qh[kc][2], qh[kc][3], l10, l11);
                mma16816(sb, ql[kc][0], ql[kc][1], ql[kc][2], ql[kc][3], h10, h11);
            }
        }

        if (kt >= 2 * qt) {
            const int r0 = qt * 128 + m0 + g;
            const int r1 = r0 + 8;
#pragma unroll
            for (int fn = 0; fn < 8; fn++) {
                const int c0 = kt * 64 + fn * 8 + 2 * t;
                if (c0 > r0)     s[fn][0] = NEG_BIG;
                if (c0 + 1 > r0) s[fn][1] = NEG_BIG;
                if (c0 > r1)     s[fn][2] = NEG_BIG;
                if (c0 + 1 > r1) s[fn][3] = NEG_BIG;
            }
        }

        float mx0 = s[0][0], mx1 = s[0][2];
#pragma unroll
        for (int fn = 0; fn < 8; fn++) {
            mx0 = fmaxf(mx0, fmaxf(s[fn][0], s[fn][1]));
            mx1 = fmaxf(mx1, fmaxf(s[fn][2], s[fn][3]));
        }
        mx0 = fmaxf(mx0, __shfl_xor_sync(0xffffffffu, mx0, 1));
        mx0 = fmaxf(mx0, __shfl_xor_sync(0xffffffffu, mx0, 2));
        mx1 = fmaxf(mx1, __shfl_xor_sync(0xffffffffu, mx1, 1));
        mx1 = fmaxf(mx1, __shfl_xor_sync(0xffffffffu, mx1, 2));

        const float mn0 = fmaxf(m_0, mx0), mn1 = fmaxf(m_1, mx1);
        const float cr0 = __expf(m_0 - mn0), cr1 = __expf(m_1 - mn1);
        m_0 = mn0; m_1 = mn1;

        float sum0 = 0.f, sum1 = 0.f;
#pragma unroll
        for (int fn = 0; fn < 8; fn++) {
            s[fn][0] = __expf(s[fn][0] - mn0);
            s[fn][1] = __expf(s[fn][1] - mn0);
            s[fn][2] = __expf(s[fn][2] - mn1);
            s[fn][3] = __expf(s[fn][3] - mn1);
            sum0 += s[fn][0] + s[fn][1];
            sum1 += s[fn][2] + s[fn][3];
        }
        sum0 += __shfl_xor_sync(0xffffffffu, sum0, 1);
        sum0 += __shfl_xor_sync(0xffffffffu, sum0, 2);
        sum1 += __shfl_xor_sync(0xffffffffu, sum1, 1);
        sum1 += __shfl_xor_sync(0xffffffffu, sum1, 2);
        l_0 = l_0 * cr0 + sum0;
        l_1 = l_1 * cr1 + sum1;

#pragma unroll
        for (int fn = 0; fn < 8; fn++) {
            oacc[fn][0] *= cr0; oacc[fn][1] *= cr0;
            oacc[fn][2] *= cr1; oacc[fn][3] *= cr1;
        }

        uint32_t ph[8], ph2[8], pl[8], pl2[8];
#pragma unroll
        for (int fn = 0; fn < 8; fn++) {
            cvt_hilo2(s[fn][0], s[fn][1], ph[fn],  pl[fn]);
            cvt_hilo2(s[fn][2], s[fn][3], ph2[fn], pl2[fn]);
        }

        // ---- O += P V : 3-pass hi/lo, ldmatrix fragment loads ----
#pragma unroll
        for (int kc = 0; kc < 4; kc++) {
            const uint32_t kcoff = (uint32_t)(kc * 8) * 4u;
            const uint32_t ah0 = ph[2 * kc],      ah1 = ph2[2 * kc];
            const uint32_t ah2 = ph[2 * kc + 1],  ah3 = ph2[2 * kc + 1];
            const uint32_t al0 = pl[2 * kc],      al1 = pl2[2 * kc];
            const uint32_t al2 = pl[2 * kc + 1],  al3 = pl2[2 * kc + 1];
#pragma unroll
            for (int fnp = 0; fnp < 4; fnp++) {
                const uint32_t fo = (uint32_t)(fnp * 16 * ASTR) * 4u + kcoff;
                uint32_t h00, h01, h10, h11, l00, l01, l10, l11;
                ldsm_x4(h00, h01, h10, h11, aVh + fo);
                ldsm_x4(l00, l01, l10, l11, aVl + fo);
                float* oa = oacc[2 * fnp];
                float* ob = oacc[2 * fnp + 1];
                mma16816(oa, ah0, ah1, ah2, ah3, h00, h01);
                mma16816(oa, ah0, ah1, ah2, ah3, l00, l01);
                mma16816(oa, al0, al1, al2, al3, h00, h01);
                mma16816(ob, ah0, ah1, ah2, ah3, h10, h11);
                mma16816(ob, ah0, ah1, ah2, ah3, l10, l11);
                mma16816(ob, al0, al1, al2, al3, h10, h11);
            }
        }
    }

    const float inv0 = 1.0f / l_0, inv1 = 1.0f / l_1;
    const size_t w0 = (tokq + m0 + g) * (DMODEL / 2) + h * (DH / 2);
    const size_t w1 = w0 + 8 * (DMODEL / 2);
#pragma unroll
    for (int fn = 0; fn < 8; fn++) {
        const int wi = fn * 4 + t;
        uint32_t hh, ll;
        cvt_hilo2(oacc[fn][0] * inv0, oacc[fn][1] * inv0, hh, ll);
        AOh[w0 + wi] = hh; AOl[w0 + wi] = ll;
        cvt_hilo2(oacc[fn][2] * inv1, oacc[fn][3] * inv1, hh, ll);
        AOh[w1 + wi] = hh; AOl[w1 + wi] = ll;
    }
}

// ---------------------------------------------------------------------------
// Launch
// ---------------------------------------------------------------------------
extern "C" void kernel_launch(void* const* d_in, const int* in_sizes, int n_in,
                              void* d_out, int out_size)
{
    const float* x     = (const float*)d_in[0];
    const float* W_dq  = (const float*)d_in[1];
    const float* W_uq  = (const float*)d_in[2];
    const float* q_g   = (const float*)d_in[3];
    const float* q_b   = (const float*)d_in[4];
    const float* W_dkv = (const float*)d_in[5];
    const float* W_ukv = (const float*)d_in[6];
    const float* kv_g  = (const float*)d_in[7];
    const float* kv_b  = (const float*)d_in[8];
    const float* W_o   = (const float*)d_in[9];
    float* out = (float*)d_out;

    uint32_t *xh, *xl, *wdqh, *wdql, *wdkh, *wdkl, *wuqh, *wuql, *wukh, *wukl, *woh, *wol;
    uint32_t *cqph, *cqpl, *ckph, *ckpl, *aoh, *aol;
    float *cq, *ckv, *Qb, *KVb;
    cudaGetSymbolAddress((void**)&xh,   g_xh);   cudaGetSymbolAddress((void**)&xl,   g_xl);
    cudaGetSymbolAddress((void**)&wdqh, g_wdqh); cudaGetSymbolAddress((void**)&wdql, g_wdql);
    cudaGetSymbolAddress((void**)&wdkh, g_wdkh); cudaGetSymbolAddress((void**)&wdkl, g_wdkl);
    cudaGetSymbolAddress((void**)&wuqh, g_wuqh); cudaGetSymbolAddress((void**)&wuql, g_wuql);
    cudaGetSymbolAddress((void**)&wukh, g_wukh); cudaGetSymbolAddress((void**)&wukl, g_wukl);
    cudaGetSymbolAddress((void**)&woh,  g_woh);  cudaGetSymbolAddress((void**)&wol,  g_wol);
    cudaGetSymbolAddress((void**)&cq,   g_cq);   cudaGetSymbolAddress((void**)&ckv,  g_ckv);
    cudaGetSymbolAddress((void**)&cqph, g_cqph); cudaGetSymbolAddress((void**)&cqpl, g_cqpl);
    cudaGetSymbolAddress((void**)&ckph, g_ckph); cudaGetSymbolAddress((void**)&ckpl, g_ckpl);
    cudaGetSymbolAddress((void**)&Qb,   g_Q);    cudaGetSymbolAddress((void**)&KVb,  g_KV);
    cudaGetSymbolAddress((void**)&aoh,  g_aoh);  cudaGetSymbolAddress((void**)&aol,  g_aol);

    // ---- pack inputs ----
    pack_hilo<<<(T_TOK * DMODEL / 2 + 255) / 256, 256>>>(x, xh, xl, T_TOK * DMODEL / 2);
    pack_hilo_t<<<(PROJ * (DMODEL / 2) + 255) / 256, 256>>>(W_dq,  wdqh, wdql, PROJ, DMODEL / 2);
    pack_hilo_t<<<(PROJ * (DMODEL / 2) + 255) / 256, 256>>>(W_dkv, wdkh, wdkl, PROJ, DMODEL / 2);
    pack_hilo_t<<<(DMODEL * (PROJ / 2) + 255) / 256, 256>>>(W_uq,  wuqh, wuql, DMODEL, PROJ / 2);
    pack_hilo_t<<<(2 * DMODEL * (PROJ / 2) + 255) / 256, 256>>>(W_ukv, wukh, wukl, 2 * DMODEL, PROJ / 2);
    pack_hilo<<<(DMODEL * DMODEL / 2 + 255) / 256, 256>>>(W_o, woh, wol, DMODEL * DMODEL / 2);

    // ---- fused down-projections: cq | ckv ----
    gemm_bf<<<dim3(4, T_TOK / 128), 256>>>(xh, xl, wdqh, wdql, wdkh, wdkl,
                                           cq, ckv, PROJ, DMODEL / 2, 2);

    // ---- fused LayerNorm + pack ----
    ln256_pack<<<2 * T_TOK, 256>>>(cq, ckv, q_g, q_b, kv_g, kv_b,
                                   cqph, cqpl, ckph, ckpl);

    // ---- up-projections ----
    gemm_bf<<<dim3(DMODEL / 128, T_TOK / 128), 256>>>(cqph, cqpl, wuqh, wuql, wuqh, wuql,
                                                      Qb, Qb, DMODEL, PROJ / 2, DMODEL / 128);
    gemm_bf<<<dim3(2 * DMODEL / 128, T_TOK / 128), 256>>>(ckph, ckpl, wukh, wukl, wukh, wukl,
                                                          KVb, KVb, 2 * DMODEL, PROJ / 2, 2 * DMODEL / 128);

    // ---- attention ----
    attn_mma<<<dim3(SEQ / 128, HEADS, BATCH), 256>>>(Qb, KVb, aoh, aol);

    // ---- output projection: out = AO @ W_o^T ----
    gemm_bf<<<dim3(DMODEL / 128, T_TOK / 128), 256>>>(aoh, aol, woh, wol, woh, wol,
                                                      out, out, DMODEL, DMODEL / 2, DMODEL / 128);
}